// round 9
// baseline (speedup 1.0000x reference)
#include <cuda_runtime.h>
#include <math.h>

// ---------------------------------------------------------------------------
// Round 9: R5 architecture (TPB=256, per-phase smem staging, 2 CTA/SM) with
// R8's prepacked fragment blob (staging = pure float4 copy) and R7's tail
// (logits MMA + shuffle action combine). nt-paired LDS.128 fragment loads.
// Output: [action B*6 | vf B*128 | expout B*12] fp32.
// ---------------------------------------------------------------------------

static constexpr int ROWS = 128;
static constexpr int TPB  = 256;

// blob float2-unit offsets
static constexpr int WS0_2 = 0;       // KC=16, NT=16 -> 8192
static constexpr int WS1_2 = 8192;    // KC=16, NT=8  -> 4096
static constexpr int WV_2  = 12288;   // KC=8,  NT=16 -> 4096
static constexpr int WE1_2 = 16384;   // KC=8,  NT=16 -> 4096
static constexpr int W2_2  = 20480;   // KC=16, NT=2  -> 1024
static constexpr int G_2   = 21504;   // KC=8,  NT=1  -> 256
static constexpr int PACK_F2 = 21760;
static constexpr int PACK_F4 = PACK_F2 / 2;

// blob float4-unit offsets
static constexpr int WS0_4 = 0;       // 4096
static constexpr int WS1_4 = 4096;    // 2048
static constexpr int WV_4  = 6144;    // 2048
static constexpr int WE1_4 = 8192;    // 2048
static constexpr int W2_4  = 10240;   // 512
static constexpr int G_4   = 10752;   // 128

__device__ float4 g_pack[PACK_F4];

// smem float offsets
static constexpr int SPAN = 0;          // staged panel (max 16384 floats)
static constexpr int SW2  = 16384;      // W2 panel (2048 floats, resident)
static constexpr int SGP  = SW2 + 2048; // G panel (512 floats, resident)
static constexpr int SLG  = SGP + 512;  // logits [128][16]
static constexpr int SGT  = SLG + 2048; // gates [128][2]
static constexpr int SMEM_FLOATS = SGT + 256;
static constexpr int SMEM_BYTES  = SMEM_FLOATS * 4;   // 84992 B

__device__ __forceinline__ unsigned f2tf_u(float x) {
    unsigned u; asm("cvt.rna.tf32.f32 %0, %1;" : "=r"(u) : "f"(x)); return u;
}
__device__ __forceinline__ float tf(float x) { return __uint_as_float(f2tf_u(x)); }

__device__ __forceinline__ float tanh_fast(float x) {
    float e = __expf(2.0f * x);
    return 1.0f - 2.0f * (1.0f / (e + 1.0f));
}
__device__ __forceinline__ float softplus_fast(float x) {
    return fmaxf(x, 0.f) + log1pf(__expf(-fabsf(x)));
}

// ============================ prologue (same packing as R8) ==================
__global__ void pack_weights(const float* __restrict__ Ws0,
                             const float* __restrict__ Ws1,
                             const float* __restrict__ Wv,
                             const float* __restrict__ We1,
                             const float* __restrict__ wg,
                             const float* __restrict__ wn,
                             const float* __restrict__ We2) {
    int idx = blockIdx.x * blockDim.x + threadIdx.x;
    int lane = idx & 31, r = lane >> 2, c = lane & 3;
    float2* g2 = (float2*)g_pack;

    if (idx < 8192) {                       // Ws0: KC=16, NT=16
        int t = idx >> 5, nt = t & 15, kc = t >> 4;
        int n = nt * 8 + r, k0 = kc * 8 + c;
        int dst = WS0_2 + ((kc * 8 + (nt >> 1)) * 32 + lane) * 2 + (nt & 1);
        g2[dst] = make_float2(tf(Ws0[k0 * 128 + n]), tf(Ws0[(k0 + 4) * 128 + n]));
    } else if (idx < 12288) {               // Ws1: KC=16, NT=8
        int i = idx - 8192;
        int t = i >> 5, nt = t & 7, kc = t >> 3;
        int n = nt * 8 + r, k0 = kc * 8 + c;
        float v0 = (n < 62) ? tf(Ws1[k0 * 62 + n])       : 0.f;
        float v1 = (n < 62) ? tf(Ws1[(k0 + 4) * 62 + n]) : 0.f;
        int dst = WS1_2 + ((kc * 4 + (nt >> 1)) * 32 + lane) * 2 + (nt & 1);
        g2[dst] = make_float2(v0, v1);
    } else if (idx < 16384) {               // Wv: KC=8, NT=16
        int i = idx - 12288;
        int t = i >> 5, nt = t & 15, kc = t >> 4;
        int n = nt * 8 + r, k0 = kc * 8 + c, k1 = k0 + 4;
        float v0 = (k0 < 62) ? tf(Wv[k0 * 128 + n]) : 0.f;
        float v1 = (k1 < 62) ? tf(Wv[k1 * 128 + n]) : 0.f;
        int dst = WV_2 + ((kc * 8 + (nt >> 1)) * 32 + lane) * 2 + (nt & 1);
        g2[dst] = make_float2(v0, v1);
    } else if (idx < 20480) {               // We1: KC=8, NT=16 (cols e*64+hid)
        int i = idx - 16384;
        int t = i >> 5, nt = t & 15, kc = t >> 4;
        int n = nt * 8 + r, k0 = kc * 8 + c, k1 = k0 + 4;
        int e = n >> 6, hid = n & 63;
        float v0 = (k0 < 62) ? tf(We1[((e * 62 + k0) << 6) + hid]) : 0.f;
        float v1 = (k1 < 62) ? tf(We1[((e * 62 + k1) << 6) + hid]) : 0.f;
        int dst = WE1_2 + ((kc * 8 + (nt >> 1)) * 32 + lane) * 2 + (nt & 1);
        g2[dst] = make_float2(v0, v1);
    } else if (idx < 21504) {               // W2: KC=16, NT=2 (block-diag)
        int i = idx - 20480;
        int t = i >> 5, nt = t & 1, kc = t >> 1;
        int n = nt * 8 + r, k0 = kc * 8 + c, k1 = k0 + 4;
        float v0 = 0.f, v1 = 0.f;
        if (n < 12) {
            int e = n / 6, o = n - e * 6;
            if ((k0 >> 6) == e) v0 = tf(We2[k0 * 6 + o]);
            if ((k1 >> 6) == e) v1 = tf(We2[k1 * 6 + o]);
        }
        int dst = W2_2 + (kc * 32 + lane) * 2 + (nt & 1);
        g2[dst] = make_float2(v0, v1);
    } else if (idx < 21760) {               // G: KC=8, NT=1 (g0,g1,n0,n1)
        int i = idx - 21504;
        int kc = i >> 5;
        int n = r, k0 = kc * 8 + c, k1 = k0 + 4;
        float v0 = 0.f, v1 = 0.f;
        if (n < 2)      { if (k0 < 62) v0 = tf(wg[k0 * 2 + n]);
                          if (k1 < 62) v1 = tf(wg[k1 * 2 + n]); }
        else if (n < 4) { if (k0 < 62) v0 = tf(wn[k0 * 2 + n - 2]);
                          if (k1 < 62) v1 = tf(wn[k1 * 2 + n - 2]); }
        g2[G_2 + kc * 32 + lane] = make_float2(v0, v1);
    }
}

// ============================ main kernel helpers ============================
__device__ __forceinline__ void mma8(float d[4], unsigned a0, unsigned a1,
                                     unsigned a2, unsigned a3,
                                     unsigned b0, unsigned b1) {
    asm("mma.sync.aligned.m16n8k8.row.col.f32.tf32.tf32.f32 "
        "{%0,%1,%2,%3},{%4,%5,%6,%7},{%8,%9},{%0,%1,%2,%3};"
        : "+f"(d[0]), "+f"(d[1]), "+f"(d[2]), "+f"(d[3])
        : "r"(a0), "r"(a1), "r"(a2), "r"(a3), "r"(b0), "r"(b1));
}

__device__ __forceinline__ void frag_to_a(float (&d)[4], int lane) {
    int base = lane & ~3;
    int src  = base | ((lane & 3) >> 1);
    float v0 = __shfl_sync(0xffffffffu, d[0], src);
    float v1 = __shfl_sync(0xffffffffu, d[1], src);
    float v2 = __shfl_sync(0xffffffffu, d[2], src);
    float v3 = __shfl_sync(0xffffffffu, d[3], src);
    float w0 = __shfl_sync(0xffffffffu, d[0], src + 2);
    float w1 = __shfl_sync(0xffffffffu, d[1], src + 2);
    float w2 = __shfl_sync(0xffffffffu, d[2], src + 2);
    float w3 = __shfl_sync(0xffffffffu, d[3], src + 2);
    bool odd = lane & 1;
    d[0] = odd ? v1 : v0;
    d[1] = odd ? v3 : v2;
    d[2] = odd ? w1 : w0;
    d[3] = odd ? w3 : w2;
}

template <int KC, int NT, int UNR>
__device__ __forceinline__ void mma_panel_s(const float4* __restrict__ P,
                                            const float (&a)[KC][4],
                                            float (&acc)[NT][4], int lane) {
    constexpr int NTP = NT / 2;
#pragma unroll UNR
    for (int kc = 0; kc < KC; kc++) {
        unsigned a0 = __float_as_uint(a[kc][0]);
        unsigned a1 = __float_as_uint(a[kc][1]);
        unsigned a2 = __float_as_uint(a[kc][2]);
        unsigned a3 = __float_as_uint(a[kc][3]);
        const float4* pk = P + kc * NTP * 32 + lane;
#pragma unroll
        for (int ntp = 0; ntp < NTP; ntp++) {
            float4 q = pk[ntp * 32];
            mma8(acc[2 * ntp],     a0, a1, a2, a3,
                 __float_as_uint(q.x), __float_as_uint(q.y));
            mma8(acc[2 * ntp + 1], a0, a1, a2, a3,
                 __float_as_uint(q.z), __float_as_uint(q.w));
        }
    }
}

template <int NT> __device__ __forceinline__ void zacc(float (&acc)[NT][4]) {
#pragma unroll
    for (int i = 0; i < NT; i++)
#pragma unroll
        for (int j = 0; j < 4; j++) acc[i][j] = 0.f;
}

// cooperative float4 copy blob -> smem
__device__ __forceinline__ void copy_panel(float4* dst, const float4* src,
                                           int n4, int tid) {
    for (int i = tid; i < n4; i += TPB) dst[i] = src[i];
}

// ============================ main kernel ====================================
__global__ void __launch_bounds__(TPB, 2) mlp_fused_kernel(
    const float* __restrict__ feat,   const float* __restrict__ noise,
    const float* __restrict__ bs0,    const float* __restrict__ bs1,
    const float* __restrict__ bv,     const float* __restrict__ be1,
    const float* __restrict__ be2,
    float* __restrict__ out_action, float* __restrict__ out_vf,
    float* __restrict__ out_expout)
{
    extern __shared__ float sm[];
    float4* sPan = (float4*)(sm + SPAN);   // staged per-phase panel
    float4* sW2p = (float4*)(sm + SW2);    // W2 panel (resident)
    const float2* sGp = (const float2*)(sm + SGP);  // G panel (resident)
    float* sLg = sm + SLG;
    float* sG  = sm + SGT;

    const int tid  = threadIdx.x;
    const int lane = tid & 31;
    const int wrow = (tid >> 5) * 16;
    const int r = lane >> 2, c = lane & 3;
    const int row0 = blockIdx.x * ROWS;

    // ---- stage W2+G (resident) and Ws0 panel ----
    copy_panel((float4*)(sm + SW2), g_pack + W2_4, 640, tid);  // W2(512)+G(128)
    copy_panel(sPan, g_pack + WS0_4, 4096, tid);
    __syncthreads();

    // ================= Phase A: h = tanh(feat @ Ws0 + bs0), N=128 ==========
    float hA[16][4];
    zacc(hA);
    {
        const float* fb  = feat + (size_t)(row0 + wrow + r) * 128 + c;
        const float* fb8 = fb + 8 * 128;
#pragma unroll 4
        for (int kc = 0; kc < 16; kc++) {
            unsigned a0 = f2tf_u(fb[kc * 8]);
            unsigned a1 = f2tf_u(fb8[kc * 8]);
            unsigned a2 = f2tf_u(fb[kc * 8 + 4]);
            unsigned a3 = f2tf_u(fb8[kc * 8 + 4]);
            const float4* pk = sPan + kc * 8 * 32 + lane;
#pragma unroll
            for (int ntp = 0; ntp < 8; ntp++) {
                float4 q = pk[ntp * 32];
                mma8(hA[2 * ntp],     a0, a1, a2, a3,
                     __float_as_uint(q.x), __float_as_uint(q.y));
                mma8(hA[2 * ntp + 1], a0, a1, a2, a3,
                     __float_as_uint(q.z), __float_as_uint(q.w));
            }
        }
#pragma unroll
        for (int nt = 0; nt < 16; nt++) {
            float2 bb = *(const float2*)&bs0[nt * 8 + 2 * c];
            hA[nt][0] = tf(tanh_fast(hA[nt][0] + bb.x));
            hA[nt][1] = tf(tanh_fast(hA[nt][1] + bb.y));
            hA[nt][2] = tf(tanh_fast(hA[nt][2] + bb.x));
            hA[nt][3] = tf(tanh_fast(hA[nt][3] + bb.y));
            frag_to_a(hA[nt], lane);
        }
    }
    __syncthreads();
    copy_panel(sPan, g_pack + WS1_4, 2048, tid);
    __syncthreads();

    // ================= Phase B: latent = tanh(h @ Ws1 + bs1), N=64 =========
    float la[8][4];
    zacc(la);
    mma_panel_s<16, 8, 4>(sPan, hA, la, lane);
#pragma unroll
    for (int nt = 0; nt < 8; nt++) {
        int col = nt * 8 + 2 * c;
        float bx = (col < 62)     ? bs1[col]     : 0.f;
        float by = (col + 1 < 62) ? bs1[col + 1] : 0.f;
        la[nt][0] = tf(tanh_fast(la[nt][0] + bx));
        la[nt][1] = tf(tanh_fast(la[nt][1] + by));
        la[nt][2] = tf(tanh_fast(la[nt][2] + bx));
        la[nt][3] = tf(tanh_fast(la[nt][3] + by));
        frag_to_a(la[nt], lane);
    }

    // ============ Gating via MMA against resident G panel (N=8) ============
    {
        float g[1][4];
        zacc(g);
#pragma unroll
        for (int kc = 0; kc < 8; kc++) {
            float2 b = sGp[kc * 32 + lane];
            mma8(g[0], __float_as_uint(la[kc][0]), __float_as_uint(la[kc][1]),
                 __float_as_uint(la[kc][2]), __float_as_uint(la[kc][3]),
                 __float_as_uint(b.x), __float_as_uint(b.y));
        }
        int base = lane & ~3;
        float v00 = __shfl_sync(0xffffffffu, g[0][0], base);
        float v01 = __shfl_sync(0xffffffffu, g[0][1], base);
        float v10 = __shfl_sync(0xffffffffu, g[0][0], base + 1);
        float v11 = __shfl_sync(0xffffffffu, g[0][1], base + 1);
        float v20 = __shfl_sync(0xffffffffu, g[0][2], base);
        float v21 = __shfl_sync(0xffffffffu, g[0][3], base);
        float v30 = __shfl_sync(0xffffffffu, g[0][2], base + 1);
        float v31 = __shfl_sync(0xffffffffu, g[0][3], base + 1);
        if (c < 2) {
            float cl0 = (c == 0) ? v00 : v20;
            float cl1 = (c == 0) ? v01 : v21;
            float n0  = (c == 0) ? v10 : v30;
            float n1  = (c == 0) ? v11 : v31;
            int row = wrow + r + ((c == 0) ? 0 : 8);
            float2 nz = *(const float2*)&noise[(size_t)(row0 + row) * 2];
            float s0 = softplus_fast(n0) + 1e-2f;
            float s1 = softplus_fast(n1) + 1e-2f;
            float z0 = fmaf(nz.x, s0, cl0);
            float z1 = fmaf(nz.y, s1, cl1);
            float mx = fmaxf(z0, z1);
            float e0 = __expf(z0 - mx), e1 = __expf(z1 - mx);
            float inv = 1.f / (e0 + e1);
            sG[2 * row + 0] = e0 * inv;
            sG[2 * row + 1] = e1 * inv;
        }
    }
    __syncthreads();
    copy_panel(sPan, g_pack + WV_4, 2048, tid);
    __syncthreads();

    // ============ Phase C: latent_vf = tanh(latent @ Wv + bv), N=128 =======
    {
        float acc[16][4];
        zacc(acc);
        mma_panel_s<8, 16, 8>(sPan, la, acc, lane);
#pragma unroll
        for (int nt = 0; nt < 16; nt++) {
            int col = nt * 8 + 2 * c;
            float2 bb = *(const float2*)&bv[col];
            float2 lo, hi;
            lo.x = tanh_fast(acc[nt][0] + bb.x);
            lo.y = tanh_fast(acc[nt][1] + bb.y);
            hi.x = tanh_fast(acc[nt][2] + bb.x);
            hi.y = tanh_fast(acc[nt][3] + bb.y);
            __stcs((float2*)&out_vf[(size_t)(row0 + wrow + r) * 128 + col],     lo);
            __stcs((float2*)&out_vf[(size_t)(row0 + wrow + r + 8) * 128 + col], hi);
        }
    }
    __syncthreads();
    copy_panel(sPan, g_pack + WE1_4, 2048, tid);
    __syncthreads();

    // ========= Phase E: eh = relu(latent @ We1 + be1), N=128 ===============
    float ehA[16][4];
    zacc(ehA);
    mma_panel_s<8, 16, 8>(sPan, la, ehA, lane);
#pragma unroll
    for (int nt = 0; nt < 16; nt++) {
        int col = nt * 8 + 2 * c;
        float2 bb = *(const float2*)&be1[col];
        ehA[nt][0] = tf(fmaxf(ehA[nt][0] + bb.x, 0.f));
        ehA[nt][1] = tf(fmaxf(ehA[nt][1] + bb.y, 0.f));
        ehA[nt][2] = tf(fmaxf(ehA[nt][2] + bb.x, 0.f));
        ehA[nt][3] = tf(fmaxf(ehA[nt][3] + bb.y, 0.f));
        frag_to_a(ehA[nt], lane);
    }

    // ========= Phase F1: logits = eh @ blockdiag(We2) + be2, N=16 ==========
    {
        float lg[2][4];
        zacc(lg);
        mma_panel_s<16, 2, 4>(sW2p, ehA, lg, lane);
#pragma unroll
        for (int nt = 0; nt < 2; nt++) {
            int col = nt * 8 + 2 * c;
            float bx = (col < 12)     ? be2[col]     : 0.f;
            float by = (col + 1 < 12) ? be2[col + 1] : 0.f;
            *(float2*)&sLg[(wrow + r) * 16 + col] =
                make_float2(lg[nt][0] + bx, lg[nt][1] + by);
            *(float2*)&sLg[(wrow + r + 8) * 16 + col] =
                make_float2(lg[nt][2] + bx, lg[nt][3] + by);
        }
    }
    __syncthreads();

    // ========= Phase F2: softmax + gated combine (thread=(row,e)) ==========
    {
        int row = tid >> 1, e = tid & 1;
        const float* lp = &sLg[row * 16 + e * 6];
        float lgs[6];
#pragma unroll
        for (int o = 0; o < 6; o++) lgs[o] = lp[o];
        float m = lgs[0];
#pragma unroll
        for (int o = 1; o < 6; o++) m = fmaxf(m, lgs[o]);
        float p[6], s = 0.f;
#pragma unroll
        for (int o = 0; o < 6; o++) { p[o] = __expf(lgs[o] - m); s += p[o]; }
        float inv = 1.f / s;
        float g = sG[2 * row + e];
        size_t gbase = ((size_t)(row0 + row) * 2 + e) * 6;
        float act[6];
#pragma unroll
        for (int o = 0; o < 6; o++) {
            float po = p[o] * inv;
            __stcs(&out_expout[gbase + o], po);
            act[o] = g * po;
        }
#pragma unroll
        for (int o = 0; o < 6; o++)
            act[o] += __shfl_xor_sync(0xffffffffu, act[o], 1);
        if (e == 0) {
            size_t ab = (size_t)(row0 + row) * 6;
            __stcs(&out_action[ab + 0], act[0]);
            __stcs(&out_action[ab + 1], act[1]);
            __stcs(&out_action[ab + 2], act[2]);
            __stcs(&out_action[ab + 3], act[3]);
            __stcs(&out_action[ab + 4], act[4]);
            __stcs(&out_action[ab + 5], act[5]);
        }
    }
}

extern "C" void kernel_launch(void* const* d_in, const int* in_sizes, int n_in,
                              void* d_out, int out_size) {
    const float* feat    = (const float*)d_in[0];
    const float* noise   = (const float*)d_in[1];
    const float* Ws0     = (const float*)d_in[2];
    const float* bs0     = (const float*)d_in[3];
    const float* Ws1     = (const float*)d_in[4];
    const float* bs1     = (const float*)d_in[5];
    const float* Wv      = (const float*)d_in[6];
    const float* bv      = (const float*)d_in[7];
    const float* w_gate  = (const float*)d_in[8];
    const float* w_noise = (const float*)d_in[9];
    const float* We1     = (const float*)d_in[10];
    const float* be1     = (const float*)d_in[11];
    const float* We2     = (const float*)d_in[12];
    const float* be2     = (const float*)d_in[13];

    const int B = in_sizes[0] / 128;

    float* out        = (float*)d_out;
    float* out_action = out;                       // [B,6]
    float* out_vf     = out + (size_t)B * 6;       // [B,128]
    float* out_expout = out + (size_t)B * 134;     // [B,2,6]

    cudaFuncSetAttribute(mlp_fused_kernel,
                         cudaFuncAttributeMaxDynamicSharedMemorySize, SMEM_BYTES);

    pack_weights<<<85, 256>>>(Ws0, Ws1, Wv, We1, w_gate, w_noise, We2);
    mlp_fused_kernel<<<B / ROWS, TPB, SMEM_BYTES>>>(
        feat, noise, bs0, bs1, bv, be1, be2,
        out_action, out_vf, out_expout);
}

// round 10
// speedup vs baseline: 1.0845x; 1.0845x over previous
#include <cuda_runtime.h>
#include <math.h>

// ---------------------------------------------------------------------------
// Round 10: persistent CTAs (1/SM, TPB=512, full RF), blob->smem once per SM,
// ZERO barriers in the main loop: gating/softmax/action are warp-local via
// quad shuffles. tf32 m16n8k8, prepacked fragment panels, LDS.128.
// Output: [action B*6 | vf B*128 | expout B*12] fp32.
// ---------------------------------------------------------------------------

static constexpr int TPB = 512;
static constexpr int BLK_ROWS = 256;   // 16 warps x 16 rows

// blob float2-unit offsets
static constexpr int WS0_2 = 0;
static constexpr int WS1_2 = 8192;
static constexpr int WV_2  = 12288;
static constexpr int WE1_2 = 16384;
static constexpr int W2_2  = 20480;
static constexpr int G_2   = 21504;
static constexpr int PACK_F2 = 21760;
static constexpr int PACK_F4 = PACK_F2 / 2;

// blob float4-unit offsets
static constexpr int WS0_4 = 0;
static constexpr int WS1_4 = 4096;
static constexpr int WV_4  = 6144;
static constexpr int WE1_4 = 8192;
static constexpr int W2_4  = 10240;
static constexpr int G_4   = 10752;

__device__ float4 g_pack[PACK_F4];

static constexpr int SMEM_BYTES = PACK_F4 * 16;   // 174080

__device__ __forceinline__ unsigned f2tf_u(float x) {
    unsigned u; asm("cvt.rna.tf32.f32 %0, %1;" : "=r"(u) : "f"(x)); return u;
}
__device__ __forceinline__ float tf(float x) { return __uint_as_float(f2tf_u(x)); }

__device__ __forceinline__ float tanh_fast(float x) {
    float e = __expf(2.0f * x);
    return 1.0f - 2.0f * (1.0f / (e + 1.0f));
}
__device__ __forceinline__ float softplus_fast(float x) {
    return fmaxf(x, 0.f) + log1pf(__expf(-fabsf(x)));
}

// ============================ prologue (same packing as R8/R9) ==============
__global__ void pack_weights(const float* __restrict__ Ws0,
                             const float* __restrict__ Ws1,
                             const float* __restrict__ Wv,
                             const float* __restrict__ We1,
                             const float* __restrict__ wg,
                             const float* __restrict__ wn,
                             const float* __restrict__ We2) {
    int idx = blockIdx.x * blockDim.x + threadIdx.x;
    int lane = idx & 31, r = lane >> 2, c = lane & 3;
    float2* g2 = (float2*)g_pack;

    if (idx < 8192) {                       // Ws0: KC=16, NT=16
        int t = idx >> 5, nt = t & 15, kc = t >> 4;
        int n = nt * 8 + r, k0 = kc * 8 + c;
        int dst = WS0_2 + ((kc * 8 + (nt >> 1)) * 32 + lane) * 2 + (nt & 1);
        g2[dst] = make_float2(tf(Ws0[k0 * 128 + n]), tf(Ws0[(k0 + 4) * 128 + n]));
    } else if (idx < 12288) {               // Ws1: KC=16, NT=8
        int i = idx - 8192;
        int t = i >> 5, nt = t & 7, kc = t >> 3;
        int n = nt * 8 + r, k0 = kc * 8 + c;
        float v0 = (n < 62) ? tf(Ws1[k0 * 62 + n])       : 0.f;
        float v1 = (n < 62) ? tf(Ws1[(k0 + 4) * 62 + n]) : 0.f;
        int dst = WS1_2 + ((kc * 4 + (nt >> 1)) * 32 + lane) * 2 + (nt & 1);
        g2[dst] = make_float2(v0, v1);
    } else if (idx < 16384) {               // Wv: KC=8, NT=16
        int i = idx - 12288;
        int t = i >> 5, nt = t & 15, kc = t >> 4;
        int n = nt * 8 + r, k0 = kc * 8 + c, k1 = k0 + 4;
        float v0 = (k0 < 62) ? tf(Wv[k0 * 128 + n]) : 0.f;
        float v1 = (k1 < 62) ? tf(Wv[k1 * 128 + n]) : 0.f;
        int dst = WV_2 + ((kc * 8 + (nt >> 1)) * 32 + lane) * 2 + (nt & 1);
        g2[dst] = make_float2(v0, v1);
    } else if (idx < 20480) {               // We1: KC=8, NT=16 (cols e*64+hid)
        int i = idx - 16384;
        int t = i >> 5, nt = t & 15, kc = t >> 4;
        int n = nt * 8 + r, k0 = kc * 8 + c, k1 = k0 + 4;
        int e = n >> 6, hid = n & 63;
        float v0 = (k0 < 62) ? tf(We1[((e * 62 + k0) << 6) + hid]) : 0.f;
        float v1 = (k1 < 62) ? tf(We1[((e * 62 + k1) << 6) + hid]) : 0.f;
        int dst = WE1_2 + ((kc * 8 + (nt >> 1)) * 32 + lane) * 2 + (nt & 1);
        g2[dst] = make_float2(v0, v1);
    } else if (idx < 21504) {               // W2: KC=16, NT=2 (block-diag)
        int i = idx - 20480;
        int t = i >> 5, nt = t & 1, kc = t >> 1;
        int n = nt * 8 + r, k0 = kc * 8 + c, k1 = k0 + 4;
        float v0 = 0.f, v1 = 0.f;
        if (n < 12) {
            int e = n / 6, o = n - e * 6;
            if ((k0 >> 6) == e) v0 = tf(We2[k0 * 6 + o]);
            if ((k1 >> 6) == e) v1 = tf(We2[k1 * 6 + o]);
        }
        int dst = W2_2 + (kc * 32 + lane) * 2 + (nt & 1);
        g2[dst] = make_float2(v0, v1);
    } else if (idx < 21760) {               // G: KC=8, NT=1 (cl0,cl1,n0,n1)
        int i = idx - 21504;
        int kc = i >> 5;
        int n = r, k0 = kc * 8 + c, k1 = k0 + 4;
        float v0 = 0.f, v1 = 0.f;
        if (n < 2)      { if (k0 < 62) v0 = tf(wg[k0 * 2 + n]);
                          if (k1 < 62) v1 = tf(wg[k1 * 2 + n]); }
        else if (n < 4) { if (k0 < 62) v0 = tf(wn[k0 * 2 + n - 2]);
                          if (k1 < 62) v1 = tf(wn[k1 * 2 + n - 2]); }
        g2[G_2 + kc * 32 + lane] = make_float2(v0, v1);
    }
}

// ============================ MMA helpers ====================================
__device__ __forceinline__ void mma8(float d[4], unsigned a0, unsigned a1,
                                     unsigned a2, unsigned a3,
                                     unsigned b0, unsigned b1) {
    asm("mma.sync.aligned.m16n8k8.row.col.f32.tf32.tf32.f32 "
        "{%0,%1,%2,%3},{%4,%5,%6,%7},{%8,%9},{%0,%1,%2,%3};"
        : "+f"(d[0]), "+f"(d[1]), "+f"(d[2]), "+f"(d[3])
        : "r"(a0), "r"(a1), "r"(a2), "r"(a3), "r"(b0), "r"(b1));
}

__device__ __forceinline__ void frag_to_a(float (&d)[4], int lane) {
    int base = lane & ~3;
    int src  = base | ((lane & 3) >> 1);
    float v0 = __shfl_sync(0xffffffffu, d[0], src);
    float v1 = __shfl_sync(0xffffffffu, d[1], src);
    float v2 = __shfl_sync(0xffffffffu, d[2], src);
    float v3 = __shfl_sync(0xffffffffu, d[3], src);
    float w0 = __shfl_sync(0xffffffffu, d[0], src + 2);
    float w1 = __shfl_sync(0xffffffffu, d[1], src + 2);
    float w2 = __shfl_sync(0xffffffffu, d[2], src + 2);
    float w3 = __shfl_sync(0xffffffffu, d[3], src + 2);
    bool odd = lane & 1;
    d[0] = odd ? v1 : v0;
    d[1] = odd ? v3 : v2;
    d[2] = odd ? w1 : w0;
    d[3] = odd ? w3 : w2;
}

template <int KC, int NT, int UNR>
__device__ __forceinline__ void mma_panel_s(const float4* __restrict__ P,
                                            const float (&a)[KC][4],
                                            float (&acc)[NT][4], int lane) {
    constexpr int NTP = NT / 2;
#pragma unroll UNR
    for (int kc = 0; kc < KC; kc++) {
        unsigned a0 = __float_as_uint(a[kc][0]);
        unsigned a1 = __float_as_uint(a[kc][1]);
        unsigned a2 = __float_as_uint(a[kc][2]);
        unsigned a3 = __float_as_uint(a[kc][3]);
        const float4* pk = P + kc * NTP * 32 + lane;
#pragma unroll
        for (int ntp = 0; ntp < NTP; ntp++) {
            float4 q = pk[ntp * 32];
            mma8(acc[2 * ntp],     a0, a1, a2, a3,
                 __float_as_uint(q.x), __float_as_uint(q.y));
            mma8(acc[2 * ntp + 1], a0, a1, a2, a3,
                 __float_as_uint(q.z), __float_as_uint(q.w));
        }
    }
}

template <int NT> __device__ __forceinline__ void zacc(float (&acc)[NT][4]) {
#pragma unroll
    for (int i = 0; i < NT; i++)
#pragma unroll
        for (int j = 0; j < 4; j++) acc[i][j] = 0.f;
}

// quad reductions (lanes differing in bits 0-1)
__device__ __forceinline__ float qmax(float v) {
    v = fmaxf(v, __shfl_xor_sync(0xffffffffu, v, 1));
    v = fmaxf(v, __shfl_xor_sync(0xffffffffu, v, 2));
    return v;
}
__device__ __forceinline__ float qsum(float v) {
    v += __shfl_xor_sync(0xffffffffu, v, 1);
    v += __shfl_xor_sync(0xffffffffu, v, 2);
    return v;
}

// ============================ main kernel ====================================
__global__ void __launch_bounds__(TPB, 1) mlp_fused_kernel(
    const float* __restrict__ feat,   const float* __restrict__ noise,
    const float* __restrict__ bs0,    const float* __restrict__ bs1,
    const float* __restrict__ bv,     const float* __restrict__ be1,
    const float* __restrict__ be2,
    float* __restrict__ out_action, float* __restrict__ out_vf,
    float* __restrict__ out_expout, int nblk)
{
    extern __shared__ float4 sPk[];

    const int tid  = threadIdx.x;
    const int lane = tid & 31;
    const int wrow = (tid >> 5) * 16;
    const int r = lane >> 2, c = lane & 3;
    const int base = lane & ~3;

    // ---- one-shot blob copy ----
    for (int i = tid; i < PACK_F4; i += TPB) sPk[i] = g_pack[i];
    __syncthreads();
    const float2* sGp = (const float2*)(sPk + G_4);

    for (int blk = blockIdx.x; blk < nblk; blk += gridDim.x) {
        const int row0 = blk * BLK_ROWS;
        const int rowA = row0 + wrow + r;   // this lane's first row
        const int rowB = rowA + 8;          // second row

        // =============== Phase A: h = tanh(feat @ Ws0 + bs0) ===============
        float hA[16][4];
        zacc(hA);
        {
            const float* fb  = feat + (size_t)rowA * 128 + c;
            const float* fb8 = fb + 8 * 128;
#pragma unroll 4
            for (int kc = 0; kc < 16; kc++) {
                unsigned a0 = f2tf_u(fb[kc * 8]);
                unsigned a1 = f2tf_u(fb8[kc * 8]);
                unsigned a2 = f2tf_u(fb[kc * 8 + 4]);
                unsigned a3 = f2tf_u(fb8[kc * 8 + 4]);
                const float4* pk = sPk + WS0_4 + kc * 8 * 32 + lane;
#pragma unroll
                for (int ntp = 0; ntp < 8; ntp++) {
                    float4 q = pk[ntp * 32];
                    mma8(hA[2 * ntp],     a0, a1, a2, a3,
                         __float_as_uint(q.x), __float_as_uint(q.y));
                    mma8(hA[2 * ntp + 1], a0, a1, a2, a3,
                         __float_as_uint(q.z), __float_as_uint(q.w));
                }
            }
#pragma unroll
            for (int nt = 0; nt < 16; nt++) {
                float2 bb = *(const float2*)&bs0[nt * 8 + 2 * c];
                hA[nt][0] = tf(tanh_fast(hA[nt][0] + bb.x));
                hA[nt][1] = tf(tanh_fast(hA[nt][1] + bb.y));
                hA[nt][2] = tf(tanh_fast(hA[nt][2] + bb.x));
                hA[nt][3] = tf(tanh_fast(hA[nt][3] + bb.y));
                frag_to_a(hA[nt], lane);
            }
        }

        // =============== Phase B: latent = tanh(h @ Ws1 + bs1) =============
        float la[8][4];
        zacc(la);
        mma_panel_s<16, 8, 4>(sPk + WS1_4, hA, la, lane);
#pragma unroll
        for (int nt = 0; nt < 8; nt++) {
            int col = nt * 8 + 2 * c;
            float bx = (col < 62)     ? bs1[col]     : 0.f;
            float by = (col + 1 < 62) ? bs1[col + 1] : 0.f;
            la[nt][0] = tf(tanh_fast(la[nt][0] + bx));
            la[nt][1] = tf(tanh_fast(la[nt][1] + by));
            la[nt][2] = tf(tanh_fast(la[nt][2] + bx));
            la[nt][3] = tf(tanh_fast(la[nt][3] + by));
            frag_to_a(la[nt], lane);
        }

        // =============== Gating (warp-local, quad shuffles) ================
        float gA0, gA1, gB0, gB1;
        {
            float g[1][4];
            zacc(g);
#pragma unroll
            for (int kc = 0; kc < 8; kc++) {
                float2 b = sGp[kc * 32 + lane];
                mma8(g[0], __float_as_uint(la[kc][0]), __float_as_uint(la[kc][1]),
                     __float_as_uint(la[kc][2]), __float_as_uint(la[kc][3]),
                     __float_as_uint(b.x), __float_as_uint(b.y));
            }
            // lane base+0 holds clean (cols 0,1); lane base+1 holds noise-pre (cols 2,3)
            float cl0  = __shfl_sync(0xffffffffu, g[0][0], base);
            float cl1  = __shfl_sync(0xffffffffu, g[0][1], base);
            float cl0b = __shfl_sync(0xffffffffu, g[0][2], base);
            float cl1b = __shfl_sync(0xffffffffu, g[0][3], base);
            float n0p  = __shfl_sync(0xffffffffu, g[0][0], base + 1);
            float n1p  = __shfl_sync(0xffffffffu, g[0][1], base + 1);
            float n0pb = __shfl_sync(0xffffffffu, g[0][2], base + 1);
            float n1pb = __shfl_sync(0xffffffffu, g[0][3], base + 1);
            float2 nzA = *(const float2*)&noise[(size_t)rowA * 2];
            float2 nzB = *(const float2*)&noise[(size_t)rowB * 2];
            {
                float z0 = fmaf(nzA.x, softplus_fast(n0p) + 1e-2f, cl0);
                float z1 = fmaf(nzA.y, softplus_fast(n1p) + 1e-2f, cl1);
                float mx = fmaxf(z0, z1);
                float e0 = __expf(z0 - mx), e1 = __expf(z1 - mx);
                float inv = 1.f / (e0 + e1);
                gA0 = e0 * inv; gA1 = e1 * inv;
            }
            {
                float z0 = fmaf(nzB.x, softplus_fast(n0pb) + 1e-2f, cl0b);
                float z1 = fmaf(nzB.y, softplus_fast(n1pb) + 1e-2f, cl1b);
                float mx = fmaxf(z0, z1);
                float e0 = __expf(z0 - mx), e1 = __expf(z1 - mx);
                float inv = 1.f / (e0 + e1);
                gB0 = e0 * inv; gB1 = e1 * inv;
            }
        }

        // =============== Phase C: latent_vf = tanh(latent @ Wv + bv) =======
        {
            float acc[16][4];
            zacc(acc);
            mma_panel_s<8, 16, 8>(sPk + WV_4, la, acc, lane);
#pragma unroll
            for (int nt = 0; nt < 16; nt++) {
                int col = nt * 8 + 2 * c;
                float2 bb = *(const float2*)&bv[col];
                float2 lo, hi;
                lo.x = tanh_fast(acc[nt][0] + bb.x);
                lo.y = tanh_fast(acc[nt][1] + bb.y);
                hi.x = tanh_fast(acc[nt][2] + bb.x);
                hi.y = tanh_fast(acc[nt][3] + bb.y);
                __stcs((float2*)&out_vf[(size_t)rowA * 128 + col], lo);
                __stcs((float2*)&out_vf[(size_t)rowB * 128 + col], hi);
            }
        }

        // =============== Phase E: eh = relu(latent @ We1 + be1) ============
        float ehA[16][4];
        zacc(ehA);
        mma_panel_s<8, 16, 8>(sPk + WE1_4, la, ehA, lane);
#pragma unroll
        for (int nt = 0; nt < 16; nt++) {
            int col = nt * 8 + 2 * c;
            float2 bb = *(const float2*)&be1[col];
            ehA[nt][0] = tf(fmaxf(ehA[nt][0] + bb.x, 0.f));
            ehA[nt][1] = tf(fmaxf(ehA[nt][1] + bb.y, 0.f));
            ehA[nt][2] = tf(fmaxf(ehA[nt][2] + bb.x, 0.f));
            ehA[nt][3] = tf(fmaxf(ehA[nt][3] + bb.y, 0.f));
            frag_to_a(ehA[nt], lane);
        }

        // =============== Phase F1: logits = eh @ blockdiag(We2)+be2 ========
        float lg[2][4];
        zacc(lg);
        mma_panel_s<16, 2, 4>(sPk + W2_4, ehA, lg, lane);
#pragma unroll
        for (int nt = 0; nt < 2; nt++) {
            int col = nt * 8 + 2 * c;
            float bx = (col < 12)     ? be2[col]     : 0.f;
            float by = (col + 1 < 12) ? be2[col + 1] : 0.f;
            lg[nt][0] += bx; lg[nt][1] += by;
            lg[nt][2] += bx; lg[nt][3] += by;
        }

        // =============== Phase F2: warp-local softmax + combine ============
        // lane (r,c) holds, for rows rowA (v0x) and rowB (v2x):
        //   cols 2c,2c+1 (lg[0]) and 8+2c,9+2c (lg[1]); cols>=12 are exact 0.
#pragma unroll
        for (int half = 0; half < 2; half++) {
            float v00 = lg[0][2 * half], v01 = lg[0][2 * half + 1];
            float v10 = lg[1][2 * half], v11 = lg[1][2 * half + 1];
            int row = half ? rowB : rowA;
            float g0 = half ? gB0 : gA0;
            float g1 = half ? gB1 : gA1;

            const float NEG = -1e30f;
            float me0 = (c < 3) ? fmaxf(v00, v01) : NEG;
            float me1 = (c == 3) ? fmaxf(v00, v01)
                                 : ((c < 2) ? fmaxf(v10, v11) : NEG);
            float m0 = qmax(me0), m1 = qmax(me1);

            float mn0 = (c == 3) ? m1 : m0;   // max for this lane's nt0 cols
            float p00 = __expf(v00 - mn0);
            float p01 = __expf(v01 - mn0);
            float p10 = __expf(v10 - m1);
            float p11 = __expf(v11 - m1);

            float s0l = (c < 3) ? (p00 + p01) : 0.f;
            float s1l = (c == 3) ? (p00 + p01) : ((c < 2) ? (p10 + p11) : 0.f);
            float inv0 = 1.f / qsum(s0l);
            float inv1 = 1.f / qsum(s1l);

            float in0 = (c == 3) ? inv1 : inv0;
            p00 *= in0; p01 *= in0;
            p10 *= inv1; p11 *= inv1;

            size_t eb = (size_t)row * 12;
            __stcs((float2*)&out_expout[eb + 2 * c], make_float2(p00, p01));
            if (c < 2)
                __stcs((float2*)&out_expout[eb + 8 + 2 * c], make_float2(p10, p11));

            // action: lane j(<3) holds e0 pair for cols 2j,2j+1; e1 pair for
            // output cols (2j,2j+1) lives at lane (j+3)&3 (c=3: nt0; c<2: nt1).
            float t0 = g0 * p00, t1 = g0 * p01;
            float u0 = (c == 3) ? g1 * p00 : g1 * p10;
            float u1 = (c == 3) ? g1 * p01 : g1 * p11;
            int src = base + ((c + 3) & 3);
            float w0 = __shfl_sync(0xffffffffu, u0, src);
            float w1 = __shfl_sync(0xffffffffu, u1, src);
            if (c < 3)
                __stcs((float2*)&out_action[(size_t)row * 6 + 2 * c],
                       make_float2(t0 + w0, t1 + w1));
        }
    }
}

extern "C" void kernel_launch(void* const* d_in, const int* in_sizes, int n_in,
                              void* d_out, int out_size) {
    const float* feat    = (const float*)d_in[0];
    const float* noise   = (const float*)d_in[1];
    const float* Ws0     = (const float*)d_in[2];
    const float* bs0     = (const float*)d_in[3];
    const float* Ws1     = (const float*)d_in[4];
    const float* bs1     = (const float*)d_in[5];
    const float* Wv      = (const float*)d_in[6];
    const float* bv      = (const float*)d_in[7];
    const float* w_gate  = (const float*)d_in[8];
    const float* w_noise = (const float*)d_in[9];
    const float* We1     = (const float*)d_in[10];
    const float* be1     = (const float*)d_in[11];
    const float* We2     = (const float*)d_in[12];
    const float* be2     = (const float*)d_in[13];

    const int B = in_sizes[0] / 128;
    const int nblk = B / BLK_ROWS;

    int nsm = 148;
    cudaDeviceGetAttribute(&nsm, cudaDevAttrMultiProcessorCount, 0);
    int grid = (nblk < nsm) ? nblk : nsm;

    float* out        = (float*)d_out;
    float* out_action = out;                       // [B,6]
    float* out_vf     = out + (size_t)B * 6;       // [B,128]
    float* out_expout = out + (size_t)B * 134;     // [B,2,6]

    cudaFuncSetAttribute(mlp_fused_kernel,
                         cudaFuncAttributeMaxDynamicSharedMemorySize, SMEM_BYTES);

    pack_weights<<<85, 256>>>(Ws0, Ws1, Wv, We1, w_gate, w_noise, We2);
    mlp_fused_kernel<<<grid, TPB, SMEM_BYTES>>>(
        feat, noise, bs0, bs1, bv, be1, be2,
        out_action, out_vf, out_expout, nblk);
}

// round 12
// speedup vs baseline: 1.4879x; 1.3719x over previous
#include <cuda_runtime.h>
#include <math.h>
#include <cstdint>

// ---------------------------------------------------------------------------
// Round 12: fp16 mma.sync m16n8k16 (fp32 accum). Prepacked fp16 B-fragment
// blob (85KB) fully resident in smem, 2 CTA/SM persistent, zero main-loop
// barriers, zero conversion shuffles (output frag -> next A frag is pure
// f16x2 packing). Warp-local gating/softmax/action tail (R10, proven).
// Output: [action B*6 | vf B*128 | expout B*12] fp32.
// ---------------------------------------------------------------------------

static constexpr int TPB = 256;
static constexpr int BLK_ROWS = 128;   // 8 warps x 16 rows

// blob offsets in uint4 units: [(kc*NTP+ntp)*32+lane] -> {b0e,b1e,b0o,b1o}
static constexpr int WS0_4 = 0;        // KC=8, NTP=8  -> 2048
static constexpr int WS1_4 = 2048;     // KC=8, NTP=4  -> 1024
static constexpr int WV_4  = 3072;     // KC=4, NTP=8  -> 1024
static constexpr int WE1_4 = 4096;     // KC=4, NTP=8  -> 1024
static constexpr int W2_4  = 5120;     // KC=8, NTP=1  -> 256
static constexpr int G_4   = 5376;     // KC=4, NT=1 as uint2[128] -> 64 u4
static constexpr int PACK_U4 = 5440;
static constexpr int SMEM_BYTES = PACK_U4 * 16;   // 87040

__device__ __align__(16) uint4 g_pack[PACK_U4];

__device__ __forceinline__ unsigned pack_h2(float lo, float hi) {
    unsigned p;
    asm("cvt.rn.f16x2.f32 %0, %1, %2;" : "=r"(p) : "f"(hi), "f"(lo));
    return p;
}
__device__ __forceinline__ float tanh_fast(float x) {
    float e = __expf(2.0f * x);
    return 1.0f - 2.0f * (1.0f / (e + 1.0f));
}
__device__ __forceinline__ float softplus_fast(float x) {
    return fmaxf(x, 0.f) + log1pf(__expf(-fabsf(x)));
}

// ============================ prologue =======================================
// For each paired panel item i: lane=i&31, t=i>>5, ntp=t%NTP, kc=t/NTP.
// n_even=(2*ntp)*8+r, n_odd=n_even+8, k0=kc*16+2c.
// b0 = pack(W(k0,n), W(k0+1,n)); b1 = pack(W(k0+8,n), W(k0+9,n)).
__global__ void pack_weights(const float* __restrict__ Ws0,
                             const float* __restrict__ Ws1,
                             const float* __restrict__ Wv,
                             const float* __restrict__ We1,
                             const float* __restrict__ wg,
                             const float* __restrict__ wn,
                             const float* __restrict__ We2) {
    int idx = blockIdx.x * blockDim.x + threadIdx.x;
    if (idx >= 5504) return;
    int lane, r, c;

    if (idx < 5376) {   // paired panels
        int base, NTP, panel;
        int i = idx;
        if (i < 2048)      { base = WS0_4; NTP = 8; panel = 0; }
        else if (i < 3072) { base = WS1_4; NTP = 4; panel = 1; i -= 2048; }
        else if (i < 4096) { base = WV_4;  NTP = 8; panel = 2; i -= 3072; }
        else if (i < 5120) { base = WE1_4; NTP = 8; panel = 3; i -= 4096; }
        else               { base = W2_4;  NTP = 1; panel = 4; i -= 5120; }
        lane = i & 31; r = lane >> 2; c = lane & 3;
        int t = i >> 5, ntp = t % NTP, kc = t / NTP;
        int k0 = kc * 16 + 2 * c;

        auto W = [&](int k, int n) -> float {
            switch (panel) {
                case 0: return Ws0[k * 128 + n];
                case 1: return (n < 62) ? Ws1[k * 62 + n] : 0.f;
                case 2: return (k < 62) ? Wv[k * 128 + n] : 0.f;
                case 3: {
                    int e = n >> 6, hid = n & 63;
                    return (k < 62) ? We1[((e * 62 + k) << 6) + hid] : 0.f;
                }
                default: {
                    if (n >= 12) return 0.f;
                    int e = n / 6, o = n - e * 6;
                    return ((k >> 6) == e) ? We2[e * 384 + (k & 63) * 6 + o] : 0.f;
                }
            }
        };
        uint4 q;
        int ne = (2 * ntp) * 8 + r, no = ne + 8;
        q.x = pack_h2(W(k0, ne), W(k0 + 1, ne));
        q.y = pack_h2(W(k0 + 8, ne), W(k0 + 9, ne));
        q.z = pack_h2(W(k0, no), W(k0 + 1, no));
        q.w = pack_h2(W(k0 + 8, no), W(k0 + 9, no));
        g_pack[base + (kc * NTP + ntp) * 32 + lane] = q;
    } else {            // G panel: 128 uint2, [kc][lane], n=r: g0,g1,n0,n1
        int i = idx - 5376;
        lane = i & 31; r = lane >> 2; c = lane & 3;
        int kc = i >> 5;
        int k0 = kc * 16 + 2 * c, n = r;
        auto G = [&](int k) -> float {
            if (k >= 62) return 0.f;
            if (n < 2) return wg[k * 2 + n];
            if (n < 4) return wn[k * 2 + (n - 2)];
            return 0.f;
        };
        uint2* g2 = (uint2*)(g_pack + G_4);
        g2[kc * 32 + lane] = make_uint2(pack_h2(G(k0), G(k0 + 1)),
                                        pack_h2(G(k0 + 8), G(k0 + 9)));
    }
}

// ============================ MMA helpers ====================================
__device__ __forceinline__ void mma16(float d[4], unsigned a0, unsigned a1,
                                      unsigned a2, unsigned a3,
                                      unsigned b0, unsigned b1) {
    asm("mma.sync.aligned.m16n8k16.row.col.f32.f16.f16.f32 "
        "{%0,%1,%2,%3},{%4,%5,%6,%7},{%8,%9},{%0,%1,%2,%3};"
        : "+f"(d[0]), "+f"(d[1]), "+f"(d[2]), "+f"(d[3])
        : "r"(a0), "r"(a1), "r"(a2), "r"(a3), "r"(b0), "r"(b1));
}

template <int KC, int NT, int UNR>
__device__ __forceinline__ void mma_panel_h(const uint4* __restrict__ P,
                                            const unsigned (&a)[KC][4],
                                            float (&acc)[NT][4], int lane) {
    constexpr int NTP = NT / 2;
#pragma unroll UNR
    for (int kc = 0; kc < KC; kc++) {
        const uint4* pk = P + kc * NTP * 32 + lane;
#pragma unroll
        for (int ntp = 0; ntp < NTP; ntp++) {
            uint4 q = pk[ntp * 32];
            mma16(acc[2 * ntp],     a[kc][0], a[kc][1], a[kc][2], a[kc][3], q.x, q.y);
            mma16(acc[2 * ntp + 1], a[kc][0], a[kc][1], a[kc][2], a[kc][3], q.z, q.w);
        }
    }
}

template <int NT> __device__ __forceinline__ void zacc(float (&acc)[NT][4]) {
#pragma unroll
    for (int i = 0; i < NT; i++)
#pragma unroll
        for (int j = 0; j < 4; j++) acc[i][j] = 0.f;
}

__device__ __forceinline__ float qmax(float v) {
    v = fmaxf(v, __shfl_xor_sync(0xffffffffu, v, 1));
    v = fmaxf(v, __shfl_xor_sync(0xffffffffu, v, 2));
    return v;
}
__device__ __forceinline__ float qsum(float v) {
    v += __shfl_xor_sync(0xffffffffu, v, 1);
    v += __shfl_xor_sync(0xffffffffu, v, 2);
    return v;
}

// ============================ main kernel ====================================
__global__ void __launch_bounds__(TPB, 2) mlp_fused_kernel(
    const float* __restrict__ feat,   const float* __restrict__ noise,
    const float* __restrict__ bs0,    const float* __restrict__ bs1,
    const float* __restrict__ bv,     const float* __restrict__ be1,
    const float* __restrict__ be2,
    float* __restrict__ out_action, float* __restrict__ out_vf,
    float* __restrict__ out_expout, int nblk)
{
    extern __shared__ uint4 sPk[];

    const int tid  = threadIdx.x;
    const int lane = tid & 31;
    const int wrow = (tid >> 5) * 16;
    const int r = lane >> 2, c = lane & 3;
    const int base = lane & ~3;

    // ---- one-shot blob copy (85 KB) ----
    for (int i = tid; i < PACK_U4; i += TPB) sPk[i] = g_pack[i];
    __syncthreads();
    const uint2* sG2 = (const uint2*)(sPk + G_4);

    for (int blk = blockIdx.x; blk < nblk; blk += gridDim.x) {
        const int rowA = blk * BLK_ROWS + wrow + r;
        const int rowB = rowA + 8;

        // =============== Phase A: h = tanh(feat @ Ws0 + bs0), N=128 ========
        float acc[16][4];
        zacc(acc);
        {
            const float* fA = feat + (size_t)rowA * 128;
            const float* fB = feat + (size_t)rowB * 128;
#pragma unroll 4
            for (int kc = 0; kc < 8; kc++) {
                int k0 = kc * 16 + 2 * c;
                float2 a0 = *(const float2*)(fA + k0);
                float2 a1 = *(const float2*)(fB + k0);
                float2 a2 = *(const float2*)(fA + k0 + 8);
                float2 a3 = *(const float2*)(fB + k0 + 8);
                unsigned u0 = pack_h2(a0.x, a0.y);
                unsigned u1 = pack_h2(a1.x, a1.y);
                unsigned u2 = pack_h2(a2.x, a2.y);
                unsigned u3 = pack_h2(a3.x, a3.y);
                const uint4* pk = sPk + WS0_4 + kc * 8 * 32 + lane;
#pragma unroll
                for (int ntp = 0; ntp < 8; ntp++) {
                    uint4 q = pk[ntp * 32];
                    mma16(acc[2 * ntp],     u0, u1, u2, u3, q.x, q.y);
                    mma16(acc[2 * ntp + 1], u0, u1, u2, u3, q.z, q.w);
                }
            }
        }
        // epi A: pure packing, no shuffles (tile 2k' cols = chunk k' k=2c..;
        // tile 2k'+1 cols = k=8+2c..)
        unsigned aH[8][4];
#pragma unroll
        for (int kp = 0; kp < 8; kp++) {
            float2 b0 = *(const float2*)&bs0[(2 * kp) * 8 + 2 * c];
            float2 b1 = *(const float2*)&bs0[(2 * kp + 1) * 8 + 2 * c];
            aH[kp][0] = pack_h2(tanh_fast(acc[2 * kp][0] + b0.x),
                                tanh_fast(acc[2 * kp][1] + b0.y));
            aH[kp][1] = pack_h2(tanh_fast(acc[2 * kp][2] + b0.x),
                                tanh_fast(acc[2 * kp][3] + b0.y));
            aH[kp][2] = pack_h2(tanh_fast(acc[2 * kp + 1][0] + b1.x),
                                tanh_fast(acc[2 * kp + 1][1] + b1.y));
            aH[kp][3] = pack_h2(tanh_fast(acc[2 * kp + 1][2] + b1.x),
                                tanh_fast(acc[2 * kp + 1][3] + b1.y));
        }

        // =============== Phase B: la = tanh(h @ Ws1 + bs1), N=64 ===========
        float accB[8][4];
        zacc(accB);
        mma_panel_h<8, 8, 4>(sPk + WS1_4, aH, accB, lane);
        unsigned laA[4][4];
#pragma unroll
        for (int kp = 0; kp < 4; kp++) {
            int c0 = (2 * kp) * 8 + 2 * c, c1 = (2 * kp + 1) * 8 + 2 * c;
            float b0x = (c0 < 62) ? bs1[c0] : 0.f;
            float b0y = (c0 + 1 < 62) ? bs1[c0 + 1] : 0.f;
            float b1x = (c1 < 62) ? bs1[c1] : 0.f;
            float b1y = (c1 + 1 < 62) ? bs1[c1 + 1] : 0.f;
            laA[kp][0] = pack_h2(tanh_fast(accB[2 * kp][0] + b0x),
                                 tanh_fast(accB[2 * kp][1] + b0y));
            laA[kp][1] = pack_h2(tanh_fast(accB[2 * kp][2] + b0x),
                                 tanh_fast(accB[2 * kp][3] + b0y));
            laA[kp][2] = pack_h2(tanh_fast(accB[2 * kp + 1][0] + b1x),
                                 tanh_fast(accB[2 * kp + 1][1] + b1y));
            laA[kp][3] = pack_h2(tanh_fast(accB[2 * kp + 1][2] + b1x),
                                 tanh_fast(accB[2 * kp + 1][3] + b1y));
        }

        // =============== Gating (warp-local; R10 extraction) ===============
        float gA0, gA1, gB0, gB1;
        {
            float g[4] = {0.f, 0.f, 0.f, 0.f};
#pragma unroll
            for (int kc = 0; kc < 4; kc++) {
                uint2 b = sG2[kc * 32 + lane];
                mma16(g, laA[kc][0], laA[kc][1], laA[kc][2], laA[kc][3],
                      b.x, b.y);
            }
            float cl0  = __shfl_sync(0xffffffffu, g[0], base);
            float cl1  = __shfl_sync(0xffffffffu, g[1], base);
            float cl0b = __shfl_sync(0xffffffffu, g[2], base);
            float cl1b = __shfl_sync(0xffffffffu, g[3], base);
            float n0p  = __shfl_sync(0xffffffffu, g[0], base + 1);
            float n1p  = __shfl_sync(0xffffffffu, g[1], base + 1);
            float n0pb = __shfl_sync(0xffffffffu, g[2], base + 1);
            float n1pb = __shfl_sync(0xffffffffu, g[3], base + 1);
            float2 nzA = *(const float2*)&noise[(size_t)rowA * 2];
            float2 nzB = *(const float2*)&noise[(size_t)rowB * 2];
            {
                float z0 = fmaf(nzA.x, softplus_fast(n0p) + 1e-2f, cl0);
                float z1 = fmaf(nzA.y, softplus_fast(n1p) + 1e-2f, cl1);
                float mx = fmaxf(z0, z1);
                float e0 = __expf(z0 - mx), e1 = __expf(z1 - mx);
                float inv = 1.f / (e0 + e1);
                gA0 = e0 * inv; gA1 = e1 * inv;
            }
            {
                float z0 = fmaf(nzB.x, softplus_fast(n0pb) + 1e-2f, cl0b);
                float z1 = fmaf(nzB.y, softplus_fast(n1pb) + 1e-2f, cl1b);
                float mx = fmaxf(z0, z1);
                float e0 = __expf(z0 - mx), e1 = __expf(z1 - mx);
                float inv = 1.f / (e0 + e1);
                gB0 = e0 * inv; gB1 = e1 * inv;
            }
        }

        // =============== Phase C: vf = tanh(la @ Wv + bv), N=128 ===========
        zacc(acc);
        mma_panel_h<4, 16, 4>(sPk + WV_4, laA, acc, lane);
#pragma unroll
        for (int nt = 0; nt < 16; nt++) {
            int col = nt * 8 + 2 * c;
            float2 bb = *(const float2*)&bv[col];
            float2 lo, hi;
            lo.x = tanh_fast(acc[nt][0] + bb.x);
            lo.y = tanh_fast(acc[nt][1] + bb.y);
            hi.x = tanh_fast(acc[nt][2] + bb.x);
            hi.y = tanh_fast(acc[nt][3] + bb.y);
            __stcs((float2*)&out_vf[(size_t)rowA * 128 + col], lo);
            __stcs((float2*)&out_vf[(size_t)rowB * 128 + col], hi);
        }

        // =============== Phase E: eh = relu(la @ We1 + be1), N=128 =========
        zacc(acc);
        mma_panel_h<4, 16, 4>(sPk + WE1_4, laA, acc, lane);
        unsigned ehA[8][4];
#pragma unroll
        for (int kp = 0; kp < 8; kp++) {
            float2 b0 = *(const float2*)&be1[(2 * kp) * 8 + 2 * c];
            float2 b1 = *(const float2*)&be1[(2 * kp + 1) * 8 + 2 * c];
            ehA[kp][0] = pack_h2(fmaxf(acc[2 * kp][0] + b0.x, 0.f),
                                 fmaxf(acc[2 * kp][1] + b0.y, 0.f));
            ehA[kp][1] = pack_h2(fmaxf(acc[2 * kp][2] + b0.x, 0.f),
                                 fmaxf(acc[2 * kp][3] + b0.y, 0.f));
            ehA[kp][2] = pack_h2(fmaxf(acc[2 * kp + 1][0] + b1.x, 0.f),
                                 fmaxf(acc[2 * kp + 1][1] + b1.y, 0.f));
            ehA[kp][3] = pack_h2(fmaxf(acc[2 * kp + 1][2] + b1.x, 0.f),
                                 fmaxf(acc[2 * kp + 1][3] + b1.y, 0.f));
        }

        // =============== Phase F1: logits = eh @ blockdiag(We2)+be2 ========
        float lg[2][4];
        zacc(lg);
        mma_panel_h<8, 2, 4>(sPk + W2_4, ehA, lg, lane);
#pragma unroll
        for (int nt = 0; nt < 2; nt++) {
            int col = nt * 8 + 2 * c;
            float bx = (col < 12)     ? be2[col]     : 0.f;
            float by = (col + 1 < 12) ? be2[col + 1] : 0.f;
            lg[nt][0] += bx; lg[nt][1] += by;
            lg[nt][2] += bx; lg[nt][3] += by;
        }

        // =============== Phase F2: warp-local softmax + combine (R10) ======
#pragma unroll
        for (int half = 0; half < 2; half++) {
            float v00 = lg[0][2 * half], v01 = lg[0][2 * half + 1];
            float v10 = lg[1][2 * half], v11 = lg[1][2 * half + 1];
            int row = half ? rowB : rowA;
            float g0 = half ? gB0 : gA0;
            float g1 = half ? gB1 : gA1;

            const float NEG = -1e30f;
            float me0 = (c < 3) ? fmaxf(v00, v01) : NEG;
            float me1 = (c == 3) ? fmaxf(v00, v01)
                                 : ((c < 2) ? fmaxf(v10, v11) : NEG);
            float m0 = qmax(me0), m1 = qmax(me1);

            float mn0 = (c == 3) ? m1 : m0;
            float p00 = __expf(v00 - mn0);
            float p01 = __expf(v01 - mn0);
            float p10 = __expf(v10 - m1);
            float p11 = __expf(v11 - m1);

            float s0l = (c < 3) ? (p00 + p01) : 0.f;
            float s1l = (c == 3) ? (p00 + p01) : ((c < 2) ? (p10 + p11) : 0.f);
            float inv0 = 1.f / qsum(s0l);
            float inv1 = 1.f / qsum(s1l);

            float in0 = (c == 3) ? inv1 : inv0;
            p00 *= in0; p01 *= in0;
            p10 *= inv1; p11 *= inv1;

            size_t eb = (size_t)row * 12;
            __stcs((float2*)&out_expout[eb + 2 * c], make_float2(p00, p01));
            if (c < 2)
                __stcs((float2*)&out_expout[eb + 8 + 2 * c], make_float2(p10, p11));

            float t0 = g0 * p00, t1 = g0 * p01;
            float u0 = (c == 3) ? g1 * p00 : g1 * p10;
            float u1 = (c == 3) ? g1 * p01 : g1 * p11;
            int src = base + ((c + 3) & 3);
            float w0 = __shfl_sync(0xffffffffu, u0, src);
            float w1 = __shfl_sync(0xffffffffu, u1, src);
            if (c < 3)
                __stcs((float2*)&out_action[(size_t)row * 6 + 2 * c],
                       make_float2(t0 + w0, t1 + w1));
        }
    }
}

extern "C" void kernel_launch(void* const* d_in, const int* in_sizes, int n_in,
                              void* d_out, int out_size) {
    const float* feat    = (const float*)d_in[0];
    const float* noise   = (const float*)d_in[1];
    const float* Ws0     = (const float*)d_in[2];
    const float* bs0     = (const float*)d_in[3];
    const float* Ws1     = (const float*)d_in[4];
    const float* bs1     = (const float*)d_in[5];
    const float* Wv      = (const float*)d_in[6];
    const float* bv      = (const float*)d_in[7];
    const float* w_gate  = (const float*)d_in[8];
    const float* w_noise = (const float*)d_in[9];
    const float* We1     = (const float*)d_in[10];
    const float* be1     = (const float*)d_in[11];
    const float* We2     = (const float*)d_in[12];
    const float* be2     = (const float*)d_in[13];

    const int B = in_sizes[0] / 128;
    const int nblk = B / BLK_ROWS;

    int nsm = 148;
    cudaDeviceGetAttribute(&nsm, cudaDevAttrMultiProcessorCount, 0);
    int grid = 2 * nsm;
    if (grid > nblk) grid = nblk;

    float* out        = (float*)d_out;
    float* out_action = out;                       // [B,6]
    float* out_vf     = out + (size_t)B * 6;       // [B,128]
    float* out_expout = out + (size_t)B * 134;     // [B,2,6]

    cudaFuncSetAttribute(mlp_fused_kernel,
                         cudaFuncAttributeMaxDynamicSharedMemorySize, SMEM_BYTES);

    pack_weights<<<22, 256>>>(Ws0, Ws1, Wv, We1, w_gate, w_noise, We2);
    mlp_fused_kernel<<<grid, TPB, SMEM_BYTES>>>(
        feat, noise, bs0, bs1, bv, be1, be2,
        out_action, out_vf, out_expout, nblk);
}

// round 13
// speedup vs baseline: 3.1645x; 2.1269x over previous
#include <cuda_runtime.h>
#include <math.h>
#include <cstdint>

// ---------------------------------------------------------------------------
// Round 13: R12 (fp16 m16n8k16, resident 85KB fragment blob, persistent
// 2 CTA/SM, barrier-free main loop, warp-local tail) + MUFU tanh.approx.f32
// for all tanh epilogues (5 ops -> 1 op; ~35% of issue slots removed).
// Output: [action B*6 | vf B*128 | expout B*12] fp32.
// ---------------------------------------------------------------------------

static constexpr int TPB = 256;
static constexpr int BLK_ROWS = 128;   // 8 warps x 16 rows

// blob offsets in uint4 units: [(kc*NTP+ntp)*32+lane] -> {b0e,b1e,b0o,b1o}
static constexpr int WS0_4 = 0;        // KC=8, NTP=8  -> 2048
static constexpr int WS1_4 = 2048;     // KC=8, NTP=4  -> 1024
static constexpr int WV_4  = 3072;     // KC=4, NTP=8  -> 1024
static constexpr int WE1_4 = 4096;     // KC=4, NTP=8  -> 1024
static constexpr int W2_4  = 5120;     // KC=8, NTP=1  -> 256
static constexpr int G_4   = 5376;     // KC=4, NT=1 as uint2[128] -> 64 u4
static constexpr int PACK_U4 = 5440;
static constexpr int SMEM_BYTES = PACK_U4 * 16;   // 87040

__device__ __align__(16) uint4 g_pack[PACK_U4];

__device__ __forceinline__ unsigned pack_h2(float lo, float hi) {
    unsigned p;
    asm("cvt.rn.f16x2.f32 %0, %1, %2;" : "=r"(p) : "f"(hi), "f"(lo));
    return p;
}
__device__ __forceinline__ float tanh_mufu(float x) {
    float y;
    asm("tanh.approx.f32 %0, %1;" : "=f"(y) : "f"(x));
    return y;
}
__device__ __forceinline__ float tanh_accurate(float x) {
    float e = __expf(2.0f * x);
    return 1.0f - 2.0f * (1.0f / (e + 1.0f));
}
__device__ __forceinline__ float softplus_fast(float x) {
    return fmaxf(x, 0.f) + log1pf(__expf(-fabsf(x)));
}

// ============================ prologue =======================================
__global__ void pack_weights(const float* __restrict__ Ws0,
                             const float* __restrict__ Ws1,
                             const float* __restrict__ Wv,
                             const float* __restrict__ We1,
                             const float* __restrict__ wg,
                             const float* __restrict__ wn,
                             const float* __restrict__ We2) {
    int idx = blockIdx.x * blockDim.x + threadIdx.x;
    if (idx >= 5504) return;
    int lane, r, c;

    if (idx < 5376) {   // paired panels
        int base, NTP, panel;
        int i = idx;
        if (i < 2048)      { base = WS0_4; NTP = 8; panel = 0; }
        else if (i < 3072) { base = WS1_4; NTP = 4; panel = 1; i -= 2048; }
        else if (i < 4096) { base = WV_4;  NTP = 8; panel = 2; i -= 3072; }
        else if (i < 5120) { base = WE1_4; NTP = 8; panel = 3; i -= 4096; }
        else               { base = W2_4;  NTP = 1; panel = 4; i -= 5120; }
        lane = i & 31; r = lane >> 2; c = lane & 3;
        int t = i >> 5, ntp = t % NTP, kc = t / NTP;
        int k0 = kc * 16 + 2 * c;

        auto W = [&](int k, int n) -> float {
            switch (panel) {
                case 0: return Ws0[k * 128 + n];
                case 1: return (n < 62) ? Ws1[k * 62 + n] : 0.f;
                case 2: return (k < 62) ? Wv[k * 128 + n] : 0.f;
                case 3: {
                    int e = n >> 6, hid = n & 63;
                    return (k < 62) ? We1[((e * 62 + k) << 6) + hid] : 0.f;
                }
                default: {
                    if (n >= 12) return 0.f;
                    int e = n / 6, o = n - e * 6;
                    return ((k >> 6) == e) ? We2[e * 384 + (k & 63) * 6 + o] : 0.f;
                }
            }
        };
        uint4 q;
        int ne = (2 * ntp) * 8 + r, no = ne + 8;
        q.x = pack_h2(W(k0, ne), W(k0 + 1, ne));
        q.y = pack_h2(W(k0 + 8, ne), W(k0 + 9, ne));
        q.z = pack_h2(W(k0, no), W(k0 + 1, no));
        q.w = pack_h2(W(k0 + 8, no), W(k0 + 9, no));
        g_pack[base + (kc * NTP + ntp) * 32 + lane] = q;
    } else {            // G panel: 128 uint2, [kc][lane], n=r: g0,g1,n0,n1
        int i = idx - 5376;
        lane = i & 31; r = lane >> 2; c = lane & 3;
        int kc = i >> 5;
        int k0 = kc * 16 + 2 * c, n = r;
        auto G = [&](int k) -> float {
            if (k >= 62) return 0.f;
            if (n < 2) return wg[k * 2 + n];
            if (n < 4) return wn[k * 2 + (n - 2)];
            return 0.f;
        };
        uint2* g2 = (uint2*)(g_pack + G_4);
        g2[kc * 32 + lane] = make_uint2(pack_h2(G(k0), G(k0 + 1)),
                                        pack_h2(G(k0 + 8), G(k0 + 9)));
    }
}

// ============================ MMA helpers ====================================
__device__ __forceinline__ void mma16(float d[4], unsigned a0, unsigned a1,
                                      unsigned a2, unsigned a3,
                                      unsigned b0, unsigned b1) {
    asm("mma.sync.aligned.m16n8k16.row.col.f32.f16.f16.f32 "
        "{%0,%1,%2,%3},{%4,%5,%6,%7},{%8,%9},{%0,%1,%2,%3};"
        : "+f"(d[0]), "+f"(d[1]), "+f"(d[2]), "+f"(d[3])
        : "r"(a0), "r"(a1), "r"(a2), "r"(a3), "r"(b0), "r"(b1));
}

template <int KC, int NT, int UNR>
__device__ __forceinline__ void mma_panel_h(const uint4* __restrict__ P,
                                            const unsigned (&a)[KC][4],
                                            float (&acc)[NT][4], int lane) {
    constexpr int NTP = NT / 2;
#pragma unroll UNR
    for (int kc = 0; kc < KC; kc++) {
        const uint4* pk = P + kc * NTP * 32 + lane;
#pragma unroll
        for (int ntp = 0; ntp < NTP; ntp++) {
            uint4 q = pk[ntp * 32];
            mma16(acc[2 * ntp],     a[kc][0], a[kc][1], a[kc][2], a[kc][3], q.x, q.y);
            mma16(acc[2 * ntp + 1], a[kc][0], a[kc][1], a[kc][2], a[kc][3], q.z, q.w);
        }
    }
}

template <int NT> __device__ __forceinline__ void zacc(float (&acc)[NT][4]) {
#pragma unroll
    for (int i = 0; i < NT; i++)
#pragma unroll
        for (int j = 0; j < 4; j++) acc[i][j] = 0.f;
}

__device__ __forceinline__ float qmax(float v) {
    v = fmaxf(v, __shfl_xor_sync(0xffffffffu, v, 1));
    v = fmaxf(v, __shfl_xor_sync(0xffffffffu, v, 2));
    return v;
}
__device__ __forceinline__ float qsum(float v) {
    v += __shfl_xor_sync(0xffffffffu, v, 1);
    v += __shfl_xor_sync(0xffffffffu, v, 2);
    return v;
}

// ============================ main kernel ====================================
__global__ void __launch_bounds__(TPB, 2) mlp_fused_kernel(
    const float* __restrict__ feat,   const float* __restrict__ noise,
    const float* __restrict__ bs0,    const float* __restrict__ bs1,
    const float* __restrict__ bv,     const float* __restrict__ be1,
    const float* __restrict__ be2,
    float* __restrict__ out_action, float* __restrict__ out_vf,
    float* __restrict__ out_expout, int nblk)
{
    extern __shared__ uint4 sPk[];

    const int tid  = threadIdx.x;
    const int lane = tid & 31;
    const int wrow = (tid >> 5) * 16;
    const int r = lane >> 2, c = lane & 3;
    const int base = lane & ~3;

    // ---- one-shot blob copy (85 KB) ----
    for (int i = tid; i < PACK_U4; i += TPB) sPk[i] = g_pack[i];
    __syncthreads();
    const uint2* sG2 = (const uint2*)(sPk + G_4);

    for (int blk = blockIdx.x; blk < nblk; blk += gridDim.x) {
        const int rowA = blk * BLK_ROWS + wrow + r;
        const int rowB = rowA + 8;

        // =============== Phase A: h = tanh(feat @ Ws0 + bs0), N=128 ========
        float acc[16][4];
        zacc(acc);
        {
            const float* fA = feat + (size_t)rowA * 128;
            const float* fB = feat + (size_t)rowB * 128;
#pragma unroll 4
            for (int kc = 0; kc < 8; kc++) {
                int k0 = kc * 16 + 2 * c;
                float2 a0 = *(const float2*)(fA + k0);
                float2 a1 = *(const float2*)(fB + k0);
                float2 a2 = *(const float2*)(fA + k0 + 8);
                float2 a3 = *(const float2*)(fB + k0 + 8);
                unsigned u0 = pack_h2(a0.x, a0.y);
                unsigned u1 = pack_h2(a1.x, a1.y);
                unsigned u2 = pack_h2(a2.x, a2.y);
                unsigned u3 = pack_h2(a3.x, a3.y);
                const uint4* pk = sPk + WS0_4 + kc * 8 * 32 + lane;
#pragma unroll
                for (int ntp = 0; ntp < 8; ntp++) {
                    uint4 q = pk[ntp * 32];
                    mma16(acc[2 * ntp],     u0, u1, u2, u3, q.x, q.y);
                    mma16(acc[2 * ntp + 1], u0, u1, u2, u3, q.z, q.w);
                }
            }
        }
        // epi A: MUFU tanh + pure packing (no shuffles)
        unsigned aH[8][4];
#pragma unroll
        for (int kp = 0; kp < 8; kp++) {
            float2 b0 = *(const float2*)&bs0[(2 * kp) * 8 + 2 * c];
            float2 b1 = *(const float2*)&bs0[(2 * kp + 1) * 8 + 2 * c];
            aH[kp][0] = pack_h2(tanh_mufu(acc[2 * kp][0] + b0.x),
                                tanh_mufu(acc[2 * kp][1] + b0.y));
            aH[kp][1] = pack_h2(tanh_mufu(acc[2 * kp][2] + b0.x),
                                tanh_mufu(acc[2 * kp][3] + b0.y));
            aH[kp][2] = pack_h2(tanh_mufu(acc[2 * kp + 1][0] + b1.x),
                                tanh_mufu(acc[2 * kp + 1][1] + b1.y));
            aH[kp][3] = pack_h2(tanh_mufu(acc[2 * kp + 1][2] + b1.x),
                                tanh_mufu(acc[2 * kp + 1][3] + b1.y));
        }

        // =============== Phase B: la = tanh(h @ Ws1 + bs1), N=64 ===========
        float accB[8][4];
        zacc(accB);
        mma_panel_h<8, 8, 4>(sPk + WS1_4, aH, accB, lane);
        unsigned laA[4][4];
#pragma unroll
        for (int kp = 0; kp < 4; kp++) {
            int c0 = (2 * kp) * 8 + 2 * c, c1 = (2 * kp + 1) * 8 + 2 * c;
            float b0x = (c0 < 62) ? bs1[c0] : 0.f;
            float b0y = (c0 + 1 < 62) ? bs1[c0 + 1] : 0.f;
            float b1x = (c1 < 62) ? bs1[c1] : 0.f;
            float b1y = (c1 + 1 < 62) ? bs1[c1 + 1] : 0.f;
            laA[kp][0] = pack_h2(tanh_mufu(accB[2 * kp][0] + b0x),
                                 tanh_mufu(accB[2 * kp][1] + b0y));
            laA[kp][1] = pack_h2(tanh_mufu(accB[2 * kp][2] + b0x),
                                 tanh_mufu(accB[2 * kp][3] + b0y));
            laA[kp][2] = pack_h2(tanh_mufu(accB[2 * kp + 1][0] + b1x),
                                 tanh_mufu(accB[2 * kp + 1][1] + b1y));
            laA[kp][3] = pack_h2(tanh_mufu(accB[2 * kp + 1][2] + b1x),
                                 tanh_mufu(accB[2 * kp + 1][3] + b1y));
        }

        // =============== Gating (warp-local) ===============================
        float gA0, gA1, gB0, gB1;
        {
            float g[4] = {0.f, 0.f, 0.f, 0.f};
#pragma unroll
            for (int kc = 0; kc < 4; kc++) {
                uint2 b = sG2[kc * 32 + lane];
                mma16(g, laA[kc][0], laA[kc][1], laA[kc][2], laA[kc][3],
                      b.x, b.y);
            }
            float cl0  = __shfl_sync(0xffffffffu, g[0], base);
            float cl1  = __shfl_sync(0xffffffffu, g[1], base);
            float cl0b = __shfl_sync(0xffffffffu, g[2], base);
            float cl1b = __shfl_sync(0xffffffffu, g[3], base);
            float n0p  = __shfl_sync(0xffffffffu, g[0], base + 1);
            float n1p  = __shfl_sync(0xffffffffu, g[1], base + 1);
            float n0pb = __shfl_sync(0xffffffffu, g[2], base + 1);
            float n1pb = __shfl_sync(0xffffffffu, g[3], base + 1);
            float2 nzA = *(const float2*)&noise[(size_t)rowA * 2];
            float2 nzB = *(const float2*)&noise[(size_t)rowB * 2];
            {
                float z0 = fmaf(nzA.x, softplus_fast(n0p) + 1e-2f, cl0);
                float z1 = fmaf(nzA.y, softplus_fast(n1p) + 1e-2f, cl1);
                float mx = fmaxf(z0, z1);
                float e0 = __expf(z0 - mx), e1 = __expf(z1 - mx);
                float inv = 1.f / (e0 + e1);
                gA0 = e0 * inv; gA1 = e1 * inv;
            }
            {
                float z0 = fmaf(nzB.x, softplus_fast(n0pb) + 1e-2f, cl0b);
                float z1 = fmaf(nzB.y, softplus_fast(n1pb) + 1e-2f, cl1b);
                float mx = fmaxf(z0, z1);
                float e0 = __expf(z0 - mx), e1 = __expf(z1 - mx);
                float inv = 1.f / (e0 + e1);
                gB0 = e0 * inv; gB1 = e1 * inv;
            }
        }

        // =============== Phase C: vf = tanh(la @ Wv + bv), N=128 ===========
        zacc(acc);
        mma_panel_h<4, 16, 4>(sPk + WV_4, laA, acc, lane);
#pragma unroll
        for (int nt = 0; nt < 16; nt++) {
            int col = nt * 8 + 2 * c;
            float2 bb = *(const float2*)&bv[col];
            float2 lo, hi;
            lo.x = tanh_mufu(acc[nt][0] + bb.x);
            lo.y = tanh_mufu(acc[nt][1] + bb.y);
            hi.x = tanh_mufu(acc[nt][2] + bb.x);
            hi.y = tanh_mufu(acc[nt][3] + bb.y);
            __stcs((float2*)&out_vf[(size_t)rowA * 128 + col], lo);
            __stcs((float2*)&out_vf[(size_t)rowB * 128 + col], hi);
        }

        // =============== Phase E: eh = relu(la @ We1 + be1), N=128 =========
        zacc(acc);
        mma_panel_h<4, 16, 4>(sPk + WE1_4, laA, acc, lane);
        unsigned ehA[8][4];
#pragma unroll
        for (int kp = 0; kp < 8; kp++) {
            float2 b0 = *(const float2*)&be1[(2 * kp) * 8 + 2 * c];
            float2 b1 = *(const float2*)&be1[(2 * kp + 1) * 8 + 2 * c];
            ehA[kp][0] = pack_h2(fmaxf(acc[2 * kp][0] + b0.x, 0.f),
                                 fmaxf(acc[2 * kp][1] + b0.y, 0.f));
            ehA[kp][1] = pack_h2(fmaxf(acc[2 * kp][2] + b0.x, 0.f),
                                 fmaxf(acc[2 * kp][3] + b0.y, 0.f));
            ehA[kp][2] = pack_h2(fmaxf(acc[2 * kp + 1][0] + b1.x, 0.f),
                                 fmaxf(acc[2 * kp + 1][1] + b1.y, 0.f));
            ehA[kp][3] = pack_h2(fmaxf(acc[2 * kp + 1][2] + b1.x, 0.f),
                                 fmaxf(acc[2 * kp + 1][3] + b1.y, 0.f));
        }

        // =============== Phase F1: logits = eh @ blockdiag(We2)+be2 ========
        float lg[2][4];
        zacc(lg);
        mma_panel_h<8, 2, 4>(sPk + W2_4, ehA, lg, lane);
#pragma unroll
        for (int nt = 0; nt < 2; nt++) {
            int col = nt * 8 + 2 * c;
            float bx = (col < 12)     ? be2[col]     : 0.f;
            float by = (col + 1 < 12) ? be2[col + 1] : 0.f;
            lg[nt][0] += bx; lg[nt][1] += by;
            lg[nt][2] += bx; lg[nt][3] += by;
        }

        // =============== Phase F2: warp-local softmax + combine ============
#pragma unroll
        for (int half = 0; half < 2; half++) {
            float v00 = lg[0][2 * half], v01 = lg[0][2 * half + 1];
            float v10 = lg[1][2 * half], v11 = lg[1][2 * half + 1];
            int row = half ? rowB : rowA;
            float g0 = half ? gB0 : gA0;
            float g1 = half ? gB1 : gA1;

            const float NEG = -1e30f;
            float me0 = (c < 3) ? fmaxf(v00, v01) : NEG;
            float me1 = (c == 3) ? fmaxf(v00, v01)
                                 : ((c < 2) ? fmaxf(v10, v11) : NEG);
            float m0 = qmax(me0), m1 = qmax(me1);

            float mn0 = (c == 3) ? m1 : m0;
            float p00 = __expf(v00 - mn0);
            float p01 = __expf(v01 - mn0);
            float p10 = __expf(v10 - m1);
            float p11 = __expf(v11 - m1);

            float s0l = (c < 3) ? (p00 + p01) : 0.f;
            float s1l = (c == 3) ? (p00 + p01) : ((c < 2) ? (p10 + p11) : 0.f);
            float inv0 = 1.f / qsum(s0l);
            float inv1 = 1.f / qsum(s1l);

            float in0 = (c == 3) ? inv1 : inv0;
            p00 *= in0; p01 *= in0;
            p10 *= inv1; p11 *= inv1;

            size_t eb = (size_t)row * 12;
            __stcs((float2*)&out_expout[eb + 2 * c], make_float2(p00, p01));
            if (c < 2)
                __stcs((float2*)&out_expout[eb + 8 + 2 * c], make_float2(p10, p11));

            float t0 = g0 * p00, t1 = g0 * p01;
            float u0 = (c == 3) ? g1 * p00 : g1 * p10;
            float u1 = (c == 3) ? g1 * p01 : g1 * p11;
            int src = base + ((c + 3) & 3);
            float w0 = __shfl_sync(0xffffffffu, u0, src);
            float w1 = __shfl_sync(0xffffffffu, u1, src);
            if (c < 3)
                __stcs((float2*)&out_action[(size_t)row * 6 + 2 * c],
                       make_float2(t0 + w0, t1 + w1));
        }
    }
}

extern "C" void kernel_launch(void* const* d_in, const int* in_sizes, int n_in,
                              void* d_out, int out_size) {
    const float* feat    = (const float*)d_in[0];
    const float* noise   = (const float*)d_in[1];
    const float* Ws0     = (const float*)d_in[2];
    const float* bs0     = (const float*)d_in[3];
    const float* Ws1     = (const float*)d_in[4];
    const float* bs1     = (const float*)d_in[5];
    const float* Wv      = (const float*)d_in[6];
    const float* bv      = (const float*)d_in[7];
    const float* w_gate  = (const float*)d_in[8];
    const float* w_noise = (const float*)d_in[9];
    const float* We1     = (const float*)d_in[10];
    const float* be1     = (const float*)d_in[11];
    const float* We2     = (const float*)d_in[12];
    const float* be2     = (const float*)d_in[13];

    const int B = in_sizes[0] / 128;
    const int nblk = B / BLK_ROWS;

    int nsm = 148;
    cudaDeviceGetAttribute(&nsm, cudaDevAttrMultiProcessorCount, 0);
    int grid = 2 * nsm;
    if (grid > nblk) grid = nblk;

    float* out        = (float*)d_out;
    float* out_action = out;                       // [B,6]
    float* out_vf     = out + (size_t)B * 6;       // [B,128]
    float* out_expout = out + (size_t)B * 134;     // [B,2,6]

    cudaFuncSetAttribute(mlp_fused_kernel,
                         cudaFuncAttributeMaxDynamicSharedMemorySize, SMEM_BYTES);

    pack_weights<<<22, 256>>>(Ws0, Ws1, Wv, We1, w_gate, w_noise, We2);
    mlp_fused_kernel<<<grid, TPB, SMEM_BYTES>>>(
        feat, noise, bs0, bs1, bv, be1, be2,
        out_action, out_vf, out_expout, nblk);
}

// round 14
// speedup vs baseline: 3.3290x; 1.0520x over previous
#include <cuda_runtime.h>
#include <math.h>
#include <cstdint>

// ---------------------------------------------------------------------------
// Round 14: R13 + dual row-tile (M=32/warp): every B-fragment load feeds two
// 16-row tiles -> smem fragment traffic halved (L1 was 82%). N-split phases
// (64-col halves) cap accumulator regs; 1 CTA/SM, 255 regs, 8 warps.
// fp16 m16n8k16, MUFU tanh, resident 85KB blob, barrier-free main loop.
// Output: [action B*6 | vf B*128 | expout B*12] fp32.
// ---------------------------------------------------------------------------

static constexpr int TPB = 256;
static constexpr int BLK_ROWS = 256;   // 8 warps x 32 rows

// blob offsets in uint4 units: [(kc*NTP+ntp)*32+lane] -> {b0e,b1e,b0o,b1o}
static constexpr int WS0_4 = 0;        // KC=8, NTP=8  -> 2048
static constexpr int WS1_4 = 2048;     // KC=8, NTP=4  -> 1024
static constexpr int WV_4  = 3072;     // KC=4, NTP=8  -> 1024
static constexpr int WE1_4 = 4096;     // KC=4, NTP=8  -> 1024
static constexpr int W2_4  = 5120;     // KC=8, NTP=1  -> 256
static constexpr int G_4   = 5376;     // KC=4 as uint2[128] -> 64 u4
static constexpr int PACK_U4 = 5440;
static constexpr int SMEM_BYTES = PACK_U4 * 16;   // 87040

__device__ __align__(16) uint4 g_pack[PACK_U4];

__device__ __forceinline__ unsigned pack_h2(float lo, float hi) {
    unsigned p;
    asm("cvt.rn.f16x2.f32 %0, %1, %2;" : "=r"(p) : "f"(hi), "f"(lo));
    return p;
}
__device__ __forceinline__ float tanh_mufu(float x) {
    float y;
    asm("tanh.approx.f32 %0, %1;" : "=f"(y) : "f"(x));
    return y;
}
__device__ __forceinline__ float softplus_fast(float x) {
    return fmaxf(x, 0.f) + log1pf(__expf(-fabsf(x)));
}

// ============================ prologue (same as R13) =========================
__global__ void pack_weights(const float* __restrict__ Ws0,
                             const float* __restrict__ Ws1,
                             const float* __restrict__ Wv,
                             const float* __restrict__ We1,
                             const float* __restrict__ wg,
                             const float* __restrict__ wn,
                             const float* __restrict__ We2) {
    int idx = blockIdx.x * blockDim.x + threadIdx.x;
    if (idx >= 5504) return;
    int lane, r, c;

    if (idx < 5376) {
        int base, NTP, panel;
        int i = idx;
        if (i < 2048)      { base = WS0_4; NTP = 8; panel = 0; }
        else if (i < 3072) { base = WS1_4; NTP = 4; panel = 1; i -= 2048; }
        else if (i < 4096) { base = WV_4;  NTP = 8; panel = 2; i -= 3072; }
        else if (i < 5120) { base = WE1_4; NTP = 8; panel = 3; i -= 4096; }
        else               { base = W2_4;  NTP = 1; panel = 4; i -= 5120; }
        lane = i & 31; r = lane >> 2; c = lane & 3;
        int t = i >> 5, ntp = t % NTP, kc = t / NTP;
        int k0 = kc * 16 + 2 * c;

        auto W = [&](int k, int n) -> float {
            switch (panel) {
                case 0: return Ws0[k * 128 + n];
                case 1: return (n < 62) ? Ws1[k * 62 + n] : 0.f;
                case 2: return (k < 62) ? Wv[k * 128 + n] : 0.f;
                case 3: {
                    int e = n >> 6, hid = n & 63;
                    return (k < 62) ? We1[((e * 62 + k) << 6) + hid] : 0.f;
                }
                default: {
                    if (n >= 12) return 0.f;
                    int e = n / 6, o = n - e * 6;
                    return ((k >> 6) == e) ? We2[e * 384 + (k & 63) * 6 + o] : 0.f;
                }
            }
        };
        uint4 q;
        int ne = (2 * ntp) * 8 + r, no = ne + 8;
        q.x = pack_h2(W(k0, ne), W(k0 + 1, ne));
        q.y = pack_h2(W(k0 + 8, ne), W(k0 + 9, ne));
        q.z = pack_h2(W(k0, no), W(k0 + 1, no));
        q.w = pack_h2(W(k0 + 8, no), W(k0 + 9, no));
        g_pack[base + (kc * NTP + ntp) * 32 + lane] = q;
    } else {
        int i = idx - 5376;
        lane = i & 31; r = lane >> 2; c = lane & 3;
        int kc = i >> 5;
        int k0 = kc * 16 + 2 * c, n = r;
        auto G = [&](int k) -> float {
            if (k >= 62) return 0.f;
            if (n < 2) return wg[k * 2 + n];
            if (n < 4) return wn[k * 2 + (n - 2)];
            return 0.f;
        };
        uint2* g2 = (uint2*)(g_pack + G_4);
        g2[kc * 32 + lane] = make_uint2(pack_h2(G(k0), G(k0 + 1)),
                                        pack_h2(G(k0 + 8), G(k0 + 9)));
    }
}

// ============================ MMA helpers ====================================
__device__ __forceinline__ void mma16(float d[4], unsigned a0, unsigned a1,
                                      unsigned a2, unsigned a3,
                                      unsigned b0, unsigned b1) {
    asm("mma.sync.aligned.m16n8k16.row.col.f32.f16.f16.f32 "
        "{%0,%1,%2,%3},{%4,%5,%6,%7},{%8,%9},{%0,%1,%2,%3};"
        : "+f"(d[0]), "+f"(d[1]), "+f"(d[2]), "+f"(d[3])
        : "r"(a0), "r"(a1), "r"(a2), "r"(a3), "r"(b0), "r"(b1));
}

// dual-tile panel: one B-fragment load feeds both row tiles
template <int KC, int NTPh, int NTPtot, int UNR>
__device__ __forceinline__ void mma_dual(const uint4* __restrict__ P, int ntp0,
                                         const unsigned (&a0)[KC][4],
                                         const unsigned (&a1)[KC][4],
                                         float (&c0)[2 * NTPh][4],
                                         float (&c1)[2 * NTPh][4], int lane) {
#pragma unroll UNR
    for (int kc = 0; kc < KC; kc++) {
        const uint4* pk = P + (kc * NTPtot + ntp0) * 32 + lane;
#pragma unroll
        for (int ntp = 0; ntp < NTPh; ntp++) {
            uint4 q = pk[ntp * 32];
            mma16(c0[2 * ntp],     a0[kc][0], a0[kc][1], a0[kc][2], a0[kc][3], q.x, q.y);
            mma16(c0[2 * ntp + 1], a0[kc][0], a0[kc][1], a0[kc][2], a0[kc][3], q.z, q.w);
            mma16(c1[2 * ntp],     a1[kc][0], a1[kc][1], a1[kc][2], a1[kc][3], q.x, q.y);
            mma16(c1[2 * ntp + 1], a1[kc][0], a1[kc][1], a1[kc][2], a1[kc][3], q.z, q.w);
        }
    }
}

template <int NT> __device__ __forceinline__ void zacc(float (&acc)[NT][4]) {
#pragma unroll
    for (int i = 0; i < NT; i++)
#pragma unroll
        for (int j = 0; j < 4; j++) acc[i][j] = 0.f;
}

__device__ __forceinline__ float qmax(float v) {
    v = fmaxf(v, __shfl_xor_sync(0xffffffffu, v, 1));
    v = fmaxf(v, __shfl_xor_sync(0xffffffffu, v, 2));
    return v;
}
__device__ __forceinline__ float qsum(float v) {
    v += __shfl_xor_sync(0xffffffffu, v, 1);
    v += __shfl_xor_sync(0xffffffffu, v, 2);
    return v;
}

// ============================ main kernel ====================================
__global__ void __launch_bounds__(TPB, 1) mlp_fused_kernel(
    const float* __restrict__ feat,   const float* __restrict__ noise,
    const float* __restrict__ bs0,    const float* __restrict__ bs1,
    const float* __restrict__ bv,     const float* __restrict__ be1,
    const float* __restrict__ be2,
    float* __restrict__ out_action, float* __restrict__ out_vf,
    float* __restrict__ out_expout, int nblk)
{
    extern __shared__ uint4 sPk[];

    const int tid  = threadIdx.x;
    const int lane = tid & 31;
    const int wrow = (tid >> 5) * 32;
    const int r = lane >> 2, c = lane & 3;
    const int base = lane & ~3;

    for (int i = tid; i < PACK_U4; i += TPB) sPk[i] = g_pack[i];
    __syncthreads();
    const uint2* sG2 = (const uint2*)(sPk + G_4);

    for (int blk = blockIdx.x; blk < nblk; blk += gridDim.x) {
        const int row0 = blk * BLK_ROWS + wrow + r;   // tile0 first row
        // tile0 rows: row0, row0+8 ; tile1 rows: row0+16, row0+24

        // ---- hoist feat A-frags for both tiles (64 regs) ----
        unsigned aF0[8][4], aF1[8][4];
        {
            const float* f0 = feat + (size_t)row0 * 128;
#pragma unroll
            for (int kc = 0; kc < 8; kc++) {
                int k0 = kc * 16 + 2 * c;
                float2 x0 = *(const float2*)(f0 + k0);
                float2 x1 = *(const float2*)(f0 + 8 * 128 + k0);
                float2 x2 = *(const float2*)(f0 + k0 + 8);
                float2 x3 = *(const float2*)(f0 + 8 * 128 + k0 + 8);
                aF0[kc][0] = pack_h2(x0.x, x0.y);
                aF0[kc][1] = pack_h2(x1.x, x1.y);
                aF0[kc][2] = pack_h2(x2.x, x2.y);
                aF0[kc][3] = pack_h2(x3.x, x3.y);
                float2 y0 = *(const float2*)(f0 + 16 * 128 + k0);
                float2 y1 = *(const float2*)(f0 + 24 * 128 + k0);
                float2 y2 = *(const float2*)(f0 + 16 * 128 + k0 + 8);
                float2 y3 = *(const float2*)(f0 + 24 * 128 + k0 + 8);
                aF1[kc][0] = pack_h2(y0.x, y0.y);
                aF1[kc][1] = pack_h2(y1.x, y1.y);
                aF1[kc][2] = pack_h2(y2.x, y2.y);
                aF1[kc][3] = pack_h2(y3.x, y3.y);
            }
        }

        // =============== Phase A: h = tanh(feat @ Ws0 + bs0) — N-split =====
        unsigned aH0[8][4], aH1[8][4];
#pragma unroll
        for (int h = 0; h < 2; h++) {
            float a0[8][4], a1[8][4];
            zacc(a0); zacc(a1);
            mma_dual<8, 4, 8, 4>(sPk + WS0_4, 4 * h, aF0, aF1, a0, a1, lane);
#pragma unroll
            for (int p = 0; p < 4; p++) {
                int kp = 4 * h + p;
                float2 b0 = *(const float2*)&bs0[(2 * kp) * 8 + 2 * c];
                float2 b1 = *(const float2*)&bs0[(2 * kp + 1) * 8 + 2 * c];
                aH0[kp][0] = pack_h2(tanh_mufu(a0[2 * p][0] + b0.x),
                                     tanh_mufu(a0[2 * p][1] + b0.y));
                aH0[kp][1] = pack_h2(tanh_mufu(a0[2 * p][2] + b0.x),
                                     tanh_mufu(a0[2 * p][3] + b0.y));
                aH0[kp][2] = pack_h2(tanh_mufu(a0[2 * p + 1][0] + b1.x),
                                     tanh_mufu(a0[2 * p + 1][1] + b1.y));
                aH0[kp][3] = pack_h2(tanh_mufu(a0[2 * p + 1][2] + b1.x),
                                     tanh_mufu(a0[2 * p + 1][3] + b1.y));
                aH1[kp][0] = pack_h2(tanh_mufu(a1[2 * p][0] + b0.x),
                                     tanh_mufu(a1[2 * p][1] + b0.y));
                aH1[kp][1] = pack_h2(tanh_mufu(a1[2 * p][2] + b0.x),
                                     tanh_mufu(a1[2 * p][3] + b0.y));
                aH1[kp][2] = pack_h2(tanh_mufu(a1[2 * p + 1][0] + b1.x),
                                     tanh_mufu(a1[2 * p + 1][1] + b1.y));
                aH1[kp][3] = pack_h2(tanh_mufu(a1[2 * p + 1][2] + b1.x),
                                     tanh_mufu(a1[2 * p + 1][3] + b1.y));
            }
        }

        // =============== Phase B: la = tanh(h @ Ws1 + bs1), N=64 ===========
        unsigned laA0[4][4], laA1[4][4];
        {
            float a0[8][4], a1[8][4];
            zacc(a0); zacc(a1);
            mma_dual<8, 4, 4, 4>(sPk + WS1_4, 0, aH0, aH1, a0, a1, lane);
#pragma unroll
            for (int kp = 0; kp < 4; kp++) {
                int c0 = (2 * kp) * 8 + 2 * c, c1 = (2 * kp + 1) * 8 + 2 * c;
                float b0x = (c0 < 62) ? bs1[c0] : 0.f;
                float b0y = (c0 + 1 < 62) ? bs1[c0 + 1] : 0.f;
                float b1x = (c1 < 62) ? bs1[c1] : 0.f;
                float b1y = (c1 + 1 < 62) ? bs1[c1 + 1] : 0.f;
                laA0[kp][0] = pack_h2(tanh_mufu(a0[2 * kp][0] + b0x),
                                      tanh_mufu(a0[2 * kp][1] + b0y));
                laA0[kp][1] = pack_h2(tanh_mufu(a0[2 * kp][2] + b0x),
                                      tanh_mufu(a0[2 * kp][3] + b0y));
                laA0[kp][2] = pack_h2(tanh_mufu(a0[2 * kp + 1][0] + b1x),
                                      tanh_mufu(a0[2 * kp + 1][1] + b1y));
                laA0[kp][3] = pack_h2(tanh_mufu(a0[2 * kp + 1][2] + b1x),
                                      tanh_mufu(a0[2 * kp + 1][3] + b1y));
                laA1[kp][0] = pack_h2(tanh_mufu(a1[2 * kp][0] + b0x),
                                      tanh_mufu(a1[2 * kp][1] + b0y));
                laA1[kp][1] = pack_h2(tanh_mufu(a1[2 * kp][2] + b0x),
                                      tanh_mufu(a1[2 * kp][3] + b0y));
                laA1[kp][2] = pack_h2(tanh_mufu(a1[2 * kp + 1][0] + b1x),
                                      tanh_mufu(a1[2 * kp + 1][1] + b1y));
                laA1[kp][3] = pack_h2(tanh_mufu(a1[2 * kp + 1][2] + b1x),
                                      tanh_mufu(a1[2 * kp + 1][3] + b1y));
            }
        }

        // =============== Gating, both tiles (warp-local) ===================
        float gate[2][4];   // [tile][gA0,gA1,gB0,gB1]
#pragma unroll
        for (int t = 0; t < 2; t++) {
            float g[4] = {0.f, 0.f, 0.f, 0.f};
#pragma unroll
            for (int kc = 0; kc < 4; kc++) {
                uint2 b = sG2[kc * 32 + lane];
                if (t == 0)
                    mma16(g, laA0[kc][0], laA0[kc][1], laA0[kc][2], laA0[kc][3], b.x, b.y);
                else
                    mma16(g, laA1[kc][0], laA1[kc][1], laA1[kc][2], laA1[kc][3], b.x, b.y);
            }
            float cl0  = __shfl_sync(0xffffffffu, g[0], base);
            float cl1  = __shfl_sync(0xffffffffu, g[1], base);
            float cl0b = __shfl_sync(0xffffffffu, g[2], base);
            float cl1b = __shfl_sync(0xffffffffu, g[3], base);
            float n0p  = __shfl_sync(0xffffffffu, g[0], base + 1);
            float n1p  = __shfl_sync(0xffffffffu, g[1], base + 1);
            float n0pb = __shfl_sync(0xffffffffu, g[2], base + 1);
            float n1pb = __shfl_sync(0xffffffffu, g[3], base + 1);
            int rA = row0 + 16 * t, rB = rA + 8;
            float2 nzA = *(const float2*)&noise[(size_t)rA * 2];
            float2 nzB = *(const float2*)&noise[(size_t)rB * 2];
            {
                float z0 = fmaf(nzA.x, softplus_fast(n0p) + 1e-2f, cl0);
                float z1 = fmaf(nzA.y, softplus_fast(n1p) + 1e-2f, cl1);
                float mx = fmaxf(z0, z1);
                float e0 = __expf(z0 - mx), e1 = __expf(z1 - mx);
                float inv = 1.f / (e0 + e1);
                gate[t][0] = e0 * inv; gate[t][1] = e1 * inv;
            }
            {
                float z0 = fmaf(nzB.x, softplus_fast(n0pb) + 1e-2f, cl0b);
                float z1 = fmaf(nzB.y, softplus_fast(n1pb) + 1e-2f, cl1b);
                float mx = fmaxf(z0, z1);
                float e0 = __expf(z0 - mx), e1 = __expf(z1 - mx);
                float inv = 1.f / (e0 + e1);
                gate[t][2] = e0 * inv; gate[t][3] = e1 * inv;
            }
        }

        // =============== Phase C: vf = tanh(la @ Wv + bv) — N-split ========
#pragma unroll
        for (int h = 0; h < 2; h++) {
            float a0[8][4], a1[8][4];
            zacc(a0); zacc(a1);
            mma_dual<4, 4, 8, 4>(sPk + WV_4, 4 * h, laA0, laA1, a0, a1, lane);
#pragma unroll
            for (int nt = 0; nt < 8; nt++) {
                int col = 64 * h + nt * 8 + 2 * c;
                float2 bb = *(const float2*)&bv[col];
                float2 o00, o01, o10, o11;
                o00.x = tanh_mufu(a0[nt][0] + bb.x);
                o00.y = tanh_mufu(a0[nt][1] + bb.y);
                o01.x = tanh_mufu(a0[nt][2] + bb.x);
                o01.y = tanh_mufu(a0[nt][3] + bb.y);
                o10.x = tanh_mufu(a1[nt][0] + bb.x);
                o10.y = tanh_mufu(a1[nt][1] + bb.y);
                o11.x = tanh_mufu(a1[nt][2] + bb.x);
                o11.y = tanh_mufu(a1[nt][3] + bb.y);
                __stcs((float2*)&out_vf[(size_t)(row0) * 128 + col],      o00);
                __stcs((float2*)&out_vf[(size_t)(row0 + 8) * 128 + col],  o01);
                __stcs((float2*)&out_vf[(size_t)(row0 + 16) * 128 + col], o10);
                __stcs((float2*)&out_vf[(size_t)(row0 + 24) * 128 + col], o11);
            }
        }

        // =============== Phase E: eh = relu(la @ We1 + be1) — N-split ======
        unsigned ehA0[8][4], ehA1[8][4];
#pragma unroll
        for (int h = 0; h < 2; h++) {
            float a0[8][4], a1[8][4];
            zacc(a0); zacc(a1);
            mma_dual<4, 4, 8, 4>(sPk + WE1_4, 4 * h, laA0, laA1, a0, a1, lane);
#pragma unroll
            for (int p = 0; p < 4; p++) {
                int kp = 4 * h + p;
                float2 b0 = *(const float2*)&be1[(2 * kp) * 8 + 2 * c];
                float2 b1 = *(const float2*)&be1[(2 * kp + 1) * 8 + 2 * c];
                ehA0[kp][0] = pack_h2(fmaxf(a0[2 * p][0] + b0.x, 0.f),
                                      fmaxf(a0[2 * p][1] + b0.y, 0.f));
                ehA0[kp][1] = pack_h2(fmaxf(a0[2 * p][2] + b0.x, 0.f),
                                      fmaxf(a0[2 * p][3] + b0.y, 0.f));
                ehA0[kp][2] = pack_h2(fmaxf(a0[2 * p + 1][0] + b1.x, 0.f),
                                      fmaxf(a0[2 * p + 1][1] + b1.y, 0.f));
                ehA0[kp][3] = pack_h2(fmaxf(a0[2 * p + 1][2] + b1.x, 0.f),
                                      fmaxf(a0[2 * p + 1][3] + b1.y, 0.f));
                ehA1[kp][0] = pack_h2(fmaxf(a1[2 * p][0] + b0.x, 0.f),
                                      fmaxf(a1[2 * p][1] + b0.y, 0.f));
                ehA1[kp][1] = pack_h2(fmaxf(a1[2 * p][2] + b0.x, 0.f),
                                      fmaxf(a1[2 * p][3] + b0.y, 0.f));
                ehA1[kp][2] = pack_h2(fmaxf(a1[2 * p + 1][0] + b1.x, 0.f),
                                      fmaxf(a1[2 * p + 1][1] + b1.y, 0.f));
                ehA1[kp][3] = pack_h2(fmaxf(a1[2 * p + 1][2] + b1.x, 0.f),
                                      fmaxf(a1[2 * p + 1][3] + b1.y, 0.f));
            }
        }

        // =============== Phase F1: logits (N=16) ===========================
        float lg0[2][4], lg1[2][4];
        zacc(lg0); zacc(lg1);
        mma_dual<8, 1, 1, 4>(sPk + W2_4, 0, ehA0, ehA1, lg0, lg1, lane);
#pragma unroll
        for (int nt = 0; nt < 2; nt++) {
            int col = nt * 8 + 2 * c;
            float bx = (col < 12)     ? be2[col]     : 0.f;
            float by = (col + 1 < 12) ? be2[col + 1] : 0.f;
            lg0[nt][0] += bx; lg0[nt][1] += by; lg0[nt][2] += bx; lg0[nt][3] += by;
            lg1[nt][0] += bx; lg1[nt][1] += by; lg1[nt][2] += bx; lg1[nt][3] += by;
        }

        // =============== Phase F2: softmax + combine, both tiles ===========
#pragma unroll
        for (int t = 0; t < 2; t++) {
#pragma unroll
            for (int half = 0; half < 2; half++) {
                float v00 = t ? lg1[0][2 * half]     : lg0[0][2 * half];
                float v01 = t ? lg1[0][2 * half + 1] : lg0[0][2 * half + 1];
                float v10 = t ? lg1[1][2 * half]     : lg0[1][2 * half];
                float v11 = t ? lg1[1][2 * half + 1] : lg0[1][2 * half + 1];
                int row = row0 + 16 * t + 8 * half;
                float g0 = gate[t][2 * half + 0];
                float g1 = gate[t][2 * half + 1];

                const float NEG = -1e30f;
                float me0 = (c < 3) ? fmaxf(v00, v01) : NEG;
                float me1 = (c == 3) ? fmaxf(v00, v01)
                                     : ((c < 2) ? fmaxf(v10, v11) : NEG);
                float m0 = qmax(me0), m1 = qmax(me1);

                float mn0 = (c == 3) ? m1 : m0;
                float p00 = __expf(v00 - mn0);
                float p01 = __expf(v01 - mn0);
                float p10 = __expf(v10 - m1);
                float p11 = __expf(v11 - m1);

                float s0l = (c < 3) ? (p00 + p01) : 0.f;
                float s1l = (c == 3) ? (p00 + p01) : ((c < 2) ? (p10 + p11) : 0.f);
                float inv0 = 1.f / qsum(s0l);
                float inv1 = 1.f / qsum(s1l);

                float in0 = (c == 3) ? inv1 : inv0;
                p00 *= in0; p01 *= in0;
                p10 *= inv1; p11 *= inv1;

                size_t eb = (size_t)row * 12;
                __stcs((float2*)&out_expout[eb + 2 * c], make_float2(p00, p01));
                if (c < 2)
                    __stcs((float2*)&out_expout[eb + 8 + 2 * c], make_float2(p10, p11));

                float t0 = g0 * p00, t1 = g0 * p01;
                float u0 = (c == 3) ? g1 * p00 : g1 * p10;
                float u1 = (c == 3) ? g1 * p01 : g1 * p11;
                int src = base + ((c + 3) & 3);
                float w0 = __shfl_sync(0xffffffffu, u0, src);
                float w1 = __shfl_sync(0xffffffffu, u1, src);
                if (c < 3)
                    __stcs((float2*)&out_action[(size_t)row * 6 + 2 * c],
                           make_float2(t0 + w0, t1 + w1));
            }
        }
    }
}

extern "C" void kernel_launch(void* const* d_in, const int* in_sizes, int n_in,
                              void* d_out, int out_size) {
    const float* feat    = (const float*)d_in[0];
    const float* noise   = (const float*)d_in[1];
    const float* Ws0     = (const float*)d_in[2];
    const float* bs0     = (const float*)d_in[3];
    const float* Ws1     = (const float*)d_in[4];
    const float* bs1     = (const float*)d_in[5];
    const float* Wv      = (const float*)d_in[6];
    const float* bv      = (const float*)d_in[7];
    const float* w_gate  = (const float*)d_in[8];
    const float* w_noise = (const float*)d_in[9];
    const float* We1     = (const float*)d_in[10];
    const float* be1     = (const float*)d_in[11];
    const float* We2     = (const float*)d_in[12];
    const float* be2     = (const float*)d_in[13];

    const int B = in_sizes[0] / 128;
    const int nblk = B / BLK_ROWS;

    int nsm = 148;
    cudaDeviceGetAttribute(&nsm, cudaDevAttrMultiProcessorCount, 0);
    int grid = (nblk < nsm) ? nblk : nsm;

    float* out        = (float*)d_out;
    float* out_action = out;                       // [B,6]
    float* out_vf     = out + (size_t)B * 6;       // [B,128]
    float* out_expout = out + (size_t)B * 134;     // [B,2,6]

    cudaFuncSetAttribute(mlp_fused_kernel,
                         cudaFuncAttributeMaxDynamicSharedMemorySize, SMEM_BYTES);

    pack_weights<<<22, 256>>>(Ws0, Ws1, Wv, We1, w_gate, w_noise, We2);
    mlp_fused_kernel<<<grid, TPB, SMEM_BYTES>>>(
        feat, noise, bs0, bs1, bv, be1, be2,
        out_action, out_vf, out_expout, nblk);
}